// round 4
// baseline (speedup 1.0000x reference)
#include <cuda_runtime.h>
#include <cstdint>
#include <math.h>

// ============================================================================
// ConditionedLatentSDETransition — fp32 SIMT GEMM pipeline (double-buffered)
//
// Per Euler step (8 steps):
//   GEMM1: A1 = z @ W1^T + b1                       (4096x1024, K=512)
//   BN1 stats (two-phase deterministic column reduce over batch)
//   GEMM2: A2 = relu(bn(A1)) @ W2^T + b2            (4096x1024, K=1024)  [BN+ReLU fused into A-load]
//   BN2 stats
//   GEMM3: F  = relu(bn(A2)) @ W3^T + b3            (4096x512,  K=1024)
//   GEMMd1: T = tanh(z @ Wd1^T + bd1)               (4096x512,  K=512)   [tanh epilogue]
//   GEMMd2: g = softplus(T @ Wd2^T + bd2)+1e-5;
//           z = z + h*F + sqrt_h*g*eps[s]                                 [SDE-update epilogue]
// Final:
//   z_next = z + (ut*dt) @ B_sde^T  -> out[0 : 4096*512)
//   yt     = z_next @ C^T + (ut*dt) @ D^T -> out[4096*512 : +4096*25)
// ============================================================================

#define BM 128
#define BN 64
#define BK 16
#define AS_LD 132   // BM + 4 pad
#define WS_LD 68    // BN + 4 pad

#define BATCH 4096
#define DDIM  512
#define HDIM  1024
#define NSTEPS 8

// ---- scratch (device globals; no allocation allowed) ----
__device__ float g_zbuf[BATCH * DDIM];
__device__ float g_A1[BATCH * HDIM];
__device__ float g_A2[BATCH * HDIM];
__device__ float g_F[BATCH * DDIM];
__device__ float g_T[BATCH * DDIM];
__device__ float g_psum [64 * HDIM];
__device__ float g_psum2[64 * HDIM];
__device__ float g_scale[HDIM];
__device__ float g_shift[HDIM];

__device__ __forceinline__ float softplus_f(float x) {
    // matches jax.nn.softplus: max(x,0) + log1p(exp(-|x|))
    return fmaxf(x, 0.f) + log1pf(expf(-fabsf(x)));
}

// ---------------------------------------------------------------------------
// Tiled GEMM:  C[M,N] = transform(A)[M,K] @ W[N,K]^T  (+ bias, epilogue)
// TRANS: 0 = none, 1 = BN(scale,shift)+ReLU on A (per-K-column), 2 = A * (*dtp)
// EPI:   0 = store acc+bias
//        1 = store tanh(acc+bias)
//        2 = g = softplus(acc+bias)+1e-5;  zb += h*Fb + sqrt_h*g*Eb  (SDE update)
//        3 = val = zb + acc; zb = val; dout = val                    (final z_next)
// Double-buffered smem: exactly one __syncthreads per K-tile.
// ---------------------------------------------------------------------------
template<int TRANS, int EPI>
__global__ __launch_bounds__(256, 2)
void gemm_k(const float* __restrict__ A, const float* __restrict__ W,
            const float* __restrict__ bias, float* __restrict__ Cout,
            int M, int N, int K,
            const float* __restrict__ scl, const float* __restrict__ shf,
            const float* __restrict__ dtp,
            const float* __restrict__ Fb, const float* __restrict__ Eb,
            float* __restrict__ zb, float* __restrict__ dout)
{
    __shared__ float As[2][BK][AS_LD];
    __shared__ float Ws[2][BK][WS_LD];

    const int tid = threadIdx.x;
    const int tx  = tid & 15;        // N dir: 16 threads * 4 cols = 64
    const int ty  = tid >> 4;        // M dir: 16 threads * 8 rows = 128
    const int bm  = blockIdx.y * BM;
    const int bn  = blockIdx.x * BN;
    const int lr  = tid >> 2;        // loader row 0..63
    const int lc4 = (tid & 3) << 2;  // loader k offset {0,4,8,12}

    const float* Ap0 = A + (size_t)(bm + lr) * K + lc4;
    const float* Ap1 = Ap0 + (size_t)64 * K;
    const float* Wp  = W + (size_t)(bn + lr) * K + lc4;

    float dtv = 0.f;
    if (TRANS == 2 || EPI == 2) dtv = *dtp;

    float acc[8][4];
#pragma unroll
    for (int i = 0; i < 8; i++)
#pragma unroll
        for (int j = 0; j < 4; j++) acc[i][j] = 0.f;

    float4 a0, a1, w0;

    // ---- load k=0 tile into registers (with fused transform) ----
    a0 = *(const float4*)(Ap0);
    a1 = *(const float4*)(Ap1);
    w0 = *(const float4*)(Wp);
    if (TRANS == 1) {
        float4 sc = *(const float4*)(scl + lc4);
        float4 sf = *(const float4*)(shf + lc4);
        a0.x = fmaxf(fmaf(a0.x, sc.x, sf.x), 0.f);
        a0.y = fmaxf(fmaf(a0.y, sc.y, sf.y), 0.f);
        a0.z = fmaxf(fmaf(a0.z, sc.z, sf.z), 0.f);
        a0.w = fmaxf(fmaf(a0.w, sc.w, sf.w), 0.f);
        a1.x = fmaxf(fmaf(a1.x, sc.x, sf.x), 0.f);
        a1.y = fmaxf(fmaf(a1.y, sc.y, sf.y), 0.f);
        a1.z = fmaxf(fmaf(a1.z, sc.z, sf.z), 0.f);
        a1.w = fmaxf(fmaf(a1.w, sc.w, sf.w), 0.f);
    }
    if (TRANS == 2) {
        a0.x *= dtv; a0.y *= dtv; a0.z *= dtv; a0.w *= dtv;
        a1.x *= dtv; a1.y *= dtv; a1.z *= dtv; a1.w *= dtv;
    }

    // stage into buffer 0
    As[0][lc4 + 0][lr]      = a0.x;
    As[0][lc4 + 1][lr]      = a0.y;
    As[0][lc4 + 2][lr]      = a0.z;
    As[0][lc4 + 3][lr]      = a0.w;
    As[0][lc4 + 0][lr + 64] = a1.x;
    As[0][lc4 + 1][lr + 64] = a1.y;
    As[0][lc4 + 2][lr + 64] = a1.z;
    As[0][lc4 + 3][lr + 64] = a1.w;
    Ws[0][lc4 + 0][lr] = w0.x;
    Ws[0][lc4 + 1][lr] = w0.y;
    Ws[0][lc4 + 2][lr] = w0.z;
    Ws[0][lc4 + 3][lr] = w0.w;
    __syncthreads();

    int buf = 0;
    for (int k0 = 0; k0 < K; k0 += BK) {
        const int kn = k0 + BK;
        // prefetch next tile into registers (hides gmem latency under FFMAs)
        if (kn < K) {
            a0 = *(const float4*)(Ap0 + kn);
            a1 = *(const float4*)(Ap1 + kn);
            w0 = *(const float4*)(Wp + kn);
            if (TRANS == 1) {
                float4 sc = *(const float4*)(scl + kn + lc4);
                float4 sf = *(const float4*)(shf + kn + lc4);
                a0.x = fmaxf(fmaf(a0.x, sc.x, sf.x), 0.f);
                a0.y = fmaxf(fmaf(a0.y, sc.y, sf.y), 0.f);
                a0.z = fmaxf(fmaf(a0.z, sc.z, sf.z), 0.f);
                a0.w = fmaxf(fmaf(a0.w, sc.w, sf.w), 0.f);
                a1.x = fmaxf(fmaf(a1.x, sc.x, sf.x), 0.f);
                a1.y = fmaxf(fmaf(a1.y, sc.y, sf.y), 0.f);
                a1.z = fmaxf(fmaf(a1.z, sc.z, sf.z), 0.f);
                a1.w = fmaxf(fmaf(a1.w, sc.w, sf.w), 0.f);
            }
            if (TRANS == 2) {
                a0.x *= dtv; a0.y *= dtv; a0.z *= dtv; a0.w *= dtv;
                a1.x *= dtv; a1.y *= dtv; a1.z *= dtv; a1.w *= dtv;
            }
        }

        // compute current tile from smem[buf]
#pragma unroll
        for (int kk = 0; kk < BK; kk++) {
            float4 x0 = *(const float4*)&As[buf][kk][ty * 8];
            float4 x1 = *(const float4*)&As[buf][kk][ty * 8 + 4];
            float4 y  = *(const float4*)&Ws[buf][kk][tx * 4];
            float av[8] = {x0.x, x0.y, x0.z, x0.w, x1.x, x1.y, x1.z, x1.w};
            float bv[4] = {y.x, y.y, y.z, y.w};
#pragma unroll
            for (int i = 0; i < 8; i++)
#pragma unroll
                for (int j = 0; j < 4; j++)
                    acc[i][j] = fmaf(av[i], bv[j], acc[i][j]);
        }

        // stage next tile into the other buffer; single barrier per iteration
        if (kn < K) {
            const int nb = buf ^ 1;
            As[nb][lc4 + 0][lr]      = a0.x;
            As[nb][lc4 + 1][lr]      = a0.y;
            As[nb][lc4 + 2][lr]      = a0.z;
            As[nb][lc4 + 3][lr]      = a0.w;
            As[nb][lc4 + 0][lr + 64] = a1.x;
            As[nb][lc4 + 1][lr + 64] = a1.y;
            As[nb][lc4 + 2][lr + 64] = a1.z;
            As[nb][lc4 + 3][lr + 64] = a1.w;
            Ws[nb][lc4 + 0][lr] = w0.x;
            Ws[nb][lc4 + 1][lr] = w0.y;
            Ws[nb][lc4 + 2][lr] = w0.z;
            Ws[nb][lc4 + 3][lr] = w0.w;
            __syncthreads();
            buf = nb;
        }
    }

    // ---- epilogue ----
    const int n0 = bn + tx * 4;
    float4 bias4 = make_float4(0.f, 0.f, 0.f, 0.f);
    if (EPI != 3) bias4 = *(const float4*)(bias + n0);

    float hh = 0.f, sqh = 0.f;
    if (EPI == 2) {
        hh  = dtv * (1.f / (float)NSTEPS);
        sqh = sqrtf(fabsf(hh) + 1e-8f);
    }

#pragma unroll
    for (int i = 0; i < 8; i++) {
        const int m = bm + ty * 8 + i;
        const size_t off = (size_t)m * N + n0;
        float4 r;
        r.x = acc[i][0] + bias4.x;
        r.y = acc[i][1] + bias4.y;
        r.z = acc[i][2] + bias4.z;
        r.w = acc[i][3] + bias4.w;
        if (EPI == 0) {
            *(float4*)(Cout + off) = r;
        } else if (EPI == 1) {
            r.x = tanhf(r.x); r.y = tanhf(r.y); r.z = tanhf(r.z); r.w = tanhf(r.w);
            *(float4*)(Cout + off) = r;
        } else if (EPI == 2) {
            float4 zf = *(const float4*)(zb + off);
            float4 ff = *(const float4*)(Fb + off);
            float4 ef = *(const float4*)(Eb + off);
            float gx = softplus_f(r.x) + 1e-5f;
            float gy = softplus_f(r.y) + 1e-5f;
            float gz = softplus_f(r.z) + 1e-5f;
            float gw = softplus_f(r.w) + 1e-5f;
            zf.x = zf.x + hh * ff.x + sqh * gx * ef.x;
            zf.y = zf.y + hh * ff.y + sqh * gy * ef.y;
            zf.z = zf.z + hh * ff.z + sqh * gz * ef.z;
            zf.w = zf.w + hh * ff.w + sqh * gw * ef.w;
            *(float4*)(zb + off) = zf;
        } else { // EPI == 3
            float4 zf = *(const float4*)(zb + off);
            zf.x += acc[i][0]; zf.y += acc[i][1]; zf.z += acc[i][2]; zf.w += acc[i][3];
            *(float4*)(zb + off)   = zf;
            *(float4*)(dout + off) = zf;
        }
    }
}

// ---------------------------------------------------------------------------
// BN batch statistics (deterministic two-phase column reduction, H = 1024)
// ---------------------------------------------------------------------------
__global__ void bnstat_part(const float* __restrict__ X)
{
    __shared__ float sm1[256], sm2[256];
    const int tid = threadIdx.x;
    const int tx = tid & 31, r0 = tid >> 5;
    const int col = blockIdx.x * 32 + tx;
    const int rowbase = blockIdx.y * 64;
    float s = 0.f, s2 = 0.f;
#pragma unroll
    for (int i = 0; i < 8; i++) {
        float v = X[(size_t)(rowbase + i * 8 + r0) * HDIM + col];
        s += v;
        s2 = fmaf(v, v, s2);
    }
    sm1[tid] = s; sm2[tid] = s2;
    __syncthreads();
    if (tid < 32) {
        float a = 0.f, b = 0.f;
#pragma unroll
        for (int r = 0; r < 8; r++) { a += sm1[r * 32 + tid]; b += sm2[r * 32 + tid]; }
        g_psum [blockIdx.y * HDIM + blockIdx.x * 32 + tid] = a;
        g_psum2[blockIdx.y * HDIM + blockIdx.x * 32 + tid] = b;
    }
}

__global__ void bnstat_final(const float* __restrict__ g, const float* __restrict__ be)
{
    const int c = blockIdx.x * 256 + threadIdx.x;  // grid = 4 blocks
    float s = 0.f, s2 = 0.f;
#pragma unroll 8
    for (int r = 0; r < 64; r++) { s += g_psum[r * HDIM + c]; s2 += g_psum2[r * HDIM + c]; }
    const float mu  = s * (1.f / (float)BATCH);
    const float var = fmaf(-mu, mu, s2 * (1.f / (float)BATCH));
    const float sc  = g[c] / sqrtf(var + 1e-5f);
    g_scale[c] = sc;
    g_shift[c] = fmaf(-mu, sc, be[c]);
}

// ---------------------------------------------------------------------------
__global__ void copy_k(const float* __restrict__ s, float* __restrict__ d, int n4)
{
    for (int i = blockIdx.x * blockDim.x + threadIdx.x; i < n4; i += gridDim.x * blockDim.x)
        ((float4*)d)[i] = ((const float4*)s)[i];
}

// yt = z_next @ C^T + (ut*dt) @ D^T   -> out[4096*512 + r*25 + n]
__global__ void yt_k(const float* __restrict__ ut, const float* __restrict__ Cm,
                     const float* __restrict__ Dm, const float* __restrict__ dtp,
                     float* __restrict__ out)
{
    const int i = blockIdx.x * blockDim.x + threadIdx.x;
    if (i >= BATCH * 25) return;
    const int r = i / 25;
    const int n = i - r * 25;

    const float4* zr = (const float4*)(g_zbuf + (size_t)r * DDIM);
    const float4* cr = (const float4*)(Cm + (size_t)n * DDIM);
    float acc = 0.f;
#pragma unroll 8
    for (int k = 0; k < DDIM / 4; k++) {
        float4 a = zr[k], b = cr[k];
        acc += a.x * b.x + a.y * b.y + a.z * b.z + a.w * b.w;
    }
    const float4* ur = (const float4*)(ut + (size_t)r * 64);
    const float4* dr = (const float4*)(Dm + (size_t)n * 64);
    float acc2 = 0.f;
#pragma unroll
    for (int k = 0; k < 16; k++) {
        float4 a = ur[k], b = dr[k];
        acc2 += a.x * b.x + a.y * b.y + a.z * b.z + a.w * b.w;
    }
    out[(size_t)BATCH * DDIM + i] = acc + (*dtp) * acc2;
}

// ===========================================================================
extern "C" void kernel_launch(void* const* d_in, const int* in_sizes, int n_in,
                              void* d_out, int out_size)
{
    (void)in_sizes; (void)n_in; (void)out_size;

    const float* z_dyn = (const float*)d_in[0];
    /* d_in[1] = z_static : unused by reference */
    const float* dtp   = (const float*)d_in[2];
    const float* ut    = (const float*)d_in[3];
    const float* eps   = (const float*)d_in[4];
    const float* W1  = (const float*)d_in[5];
    const float* b1  = (const float*)d_in[6];
    const float* g1  = (const float*)d_in[7];
    const float* be1 = (const float*)d_in[8];
    const float* W2  = (const float*)d_in[9];
    const float* b2  = (const float*)d_in[10];
    const float* g2  = (const float*)d_in[11];
    const float* be2 = (const float*)d_in[12];
    const float* W3  = (const float*)d_in[13];
    const float* b3  = (const float*)d_in[14];
    const float* Wd1 = (const float*)d_in[15];
    const float* bd1 = (const float*)d_in[16];
    const float* Wd2 = (const float*)d_in[17];
    const float* bd2 = (const float*)d_in[18];
    const float* Bs  = (const float*)d_in[19];
    const float* Cm  = (const float*)d_in[20];
    const float* Dm  = (const float*)d_in[21];
    float* out = (float*)d_out;

    float *zbuf, *A1, *A2, *F, *T, *scl, *shf;
    cudaGetSymbolAddress((void**)&zbuf, g_zbuf);
    cudaGetSymbolAddress((void**)&A1,   g_A1);
    cudaGetSymbolAddress((void**)&A2,   g_A2);
    cudaGetSymbolAddress((void**)&F,    g_F);
    cudaGetSymbolAddress((void**)&T,    g_T);
    cudaGetSymbolAddress((void**)&scl,  g_scale);
    cudaGetSymbolAddress((void**)&shf,  g_shift);

    const dim3 blk(256);
    const dim3 gridH(HDIM / BN, BATCH / BM);  // N=1024 outputs
    const dim3 gridD(DDIM / BN, BATCH / BM);  // N=512 outputs
    const dim3 gridS(HDIM / 32, 64);          // BN stats phase 1

    copy_k<<<512, 256>>>(z_dyn, zbuf, BATCH * DDIM / 4);

    for (int s = 0; s < NSTEPS; s++) {
        const float* eps_s = eps + (size_t)s * BATCH * DDIM;

        // drift layer 1
        gemm_k<0, 0><<<gridH, blk>>>(zbuf, W1, b1, A1, BATCH, HDIM, DDIM,
                                     nullptr, nullptr, nullptr, nullptr, nullptr, nullptr, nullptr);
        bnstat_part<<<gridS, 256>>>(A1);
        bnstat_final<<<4, 256>>>(g1, be1);
        // drift layer 2 (BN1+ReLU fused into A load)
        gemm_k<1, 0><<<gridH, blk>>>(A1, W2, b2, A2, BATCH, HDIM, HDIM,
                                     scl, shf, nullptr, nullptr, nullptr, nullptr, nullptr);
        bnstat_part<<<gridS, 256>>>(A2);
        bnstat_final<<<4, 256>>>(g2, be2);
        // drift layer 3 (BN2+ReLU fused into A load)
        gemm_k<1, 0><<<gridD, blk>>>(A2, W3, b3, F, BATCH, DDIM, HDIM,
                                     scl, shf, nullptr, nullptr, nullptr, nullptr, nullptr);
        // diffusion layer 1 (tanh epilogue)
        gemm_k<0, 1><<<gridD, blk>>>(zbuf, Wd1, bd1, T, BATCH, DDIM, DDIM,
                                     nullptr, nullptr, nullptr, nullptr, nullptr, nullptr, nullptr);
        // diffusion layer 2 + Euler-Maruyama update (softplus epilogue, in-place z)
        gemm_k<0, 2><<<gridD, blk>>>(T, Wd2, bd2, nullptr, BATCH, DDIM, DDIM,
                                     nullptr, nullptr, dtp, F, eps_s, zbuf, nullptr);
    }

    // z_next = z + (ut*dt) @ B_sde^T  -> zbuf and out[0 : 4096*512)
    gemm_k<2, 3><<<gridD, blk>>>(ut, Bs, nullptr, nullptr, BATCH, DDIM, 64,
                                 nullptr, nullptr, dtp, nullptr, nullptr, zbuf, out);
    // yt -> out[4096*512 : +4096*25)
    yt_k<<<(BATCH * 25 + 255) / 256, 256>>>(ut, Cm, Dm, dtp, out);
}

// round 5
// speedup vs baseline: 3.4541x; 3.4541x over previous
#include <cuda_runtime.h>
#include <cstdint>
#include <math.h>

// ============================================================================
// ConditionedLatentSDETransition — tf32 tensor-core (mma.sync m16n8k8) pipeline
//
// Per Euler step (8 steps):
//   GEMM1: A1 = z @ W1^T + b1                       (4096x1024, K=512)
//   BN1 stats (two-phase deterministic column reduce)
//   GEMM2: A2 = relu(bn(A1)) @ W2^T + b2            (4096x1024, K=1024)  [BN+ReLU fused in A-staging]
//   BN2 stats
//   GEMM3: F  = relu(bn(A2)) @ W3^T + b3            (4096x512,  K=1024)
//   GEMMd1: T = tanh(z @ Wd1^T + bd1)               (4096x512,  K=512)
//   GEMMd2: g = softplus(T @ Wd2^T + bd2)+1e-5;  z += h*F + sqrt_h*g*eps[s]
// Final:
//   z_next = z + (ut*dt) @ B_sde^T -> out[0:4096*512)
//   yt     = z_next @ C^T + (ut*dt) @ D^T -> out[4096*512:+4096*25)
// ============================================================================

#define BM 128
#define BN 128
#define BK 16
#define KS_LD 20    // BK + 4 pad (bank-conflict-free: (20g+q) mod 32 all-distinct)

#define BATCH 4096
#define DDIM  512
#define HDIM  1024
#define NSTEPS 8

// ---- scratch (device globals; no allocation allowed) ----
__device__ float g_zbuf[BATCH * DDIM];
__device__ float g_A1[BATCH * HDIM];
__device__ float g_A2[BATCH * HDIM];
__device__ float g_F[BATCH * DDIM];
__device__ float g_T[BATCH * DDIM];
__device__ float g_psum [64 * HDIM];
__device__ float g_psum2[64 * HDIM];
__device__ float g_scale[HDIM];
__device__ float g_shift[HDIM];

__device__ __forceinline__ float softplus_f(float x) {
    return fmaxf(x, 0.f) + log1pf(expf(-fabsf(x)));   // jax.nn.softplus
}

__device__ __forceinline__ uint32_t f2tf(float f) {
    uint32_t u;
    asm("cvt.rna.tf32.f32 %0, %1;" : "=r"(u) : "f"(f));
    return u;
}
__device__ __forceinline__ uint4 cvt4(float4 v) {
    return make_uint4(f2tf(v.x), f2tf(v.y), f2tf(v.z), f2tf(v.w));
}

__device__ __forceinline__ void mma_tf32(float* c, const uint32_t* a, const uint32_t* b) {
    asm volatile(
        "mma.sync.aligned.m16n8k8.row.col.f32.tf32.tf32.f32 "
        "{%0,%1,%2,%3}, {%4,%5,%6,%7}, {%8,%9}, {%0,%1,%2,%3};\n"
        : "+f"(c[0]), "+f"(c[1]), "+f"(c[2]), "+f"(c[3])
        : "r"(a[0]), "r"(a[1]), "r"(a[2]), "r"(a[3]), "r"(b[0]), "r"(b[1]));
}

// ---------------------------------------------------------------------------
// Tensor-core GEMM:  C[M,N] = transform(A)[M,K] @ W[N,K]^T  (+ bias, epilogue)
// TRANS: 0 = none, 1 = BN(scale,shift)+ReLU on A (per-K-col, fp32 pre-convert),
//        2 = A * (*dtp)
// EPI:   0 = store acc+bias
//        1 = store tanh(acc+bias)
//        2 = g = softplus(acc+bias)+1e-5;  zb += h*Fb + sqrt_h*g*Eb   (SDE update)
//        3 = val = zb + acc; zb = val; dout = val                     (final z_next)
// CTA 128x128x16, 8 warps (warp tile 64x32 = 4x4 m16n8 tiles), double-buffered.
// ---------------------------------------------------------------------------
template<int TRANS, int EPI>
__global__ __launch_bounds__(256, 2)
void gemm_tc(const float* __restrict__ A, const float* __restrict__ W,
             const float* __restrict__ bias, float* __restrict__ Cout,
             int M, int N, int K,
             const float* __restrict__ scl, const float* __restrict__ shf,
             const float* __restrict__ dtp,
             const float* __restrict__ Fb, const float* __restrict__ Eb,
             float* __restrict__ zb, float* __restrict__ dout)
{
    __shared__ uint32_t As[2][BM][KS_LD];
    __shared__ uint32_t Bs[2][BN][KS_LD];

    const int tid  = threadIdx.x;
    const int lane = tid & 31;
    const int wid  = tid >> 5;
    const int wm   = wid >> 2;          // 0..1  -> M offset wm*64
    const int wn   = wid & 3;           // 0..3  -> N offset wn*32
    const int grp  = lane >> 2;         // 0..7
    const int qk   = lane & 3;          // 0..3
    const int bm   = blockIdx.y * BM;
    const int bn   = blockIdx.x * BN;

    const int lrow = tid >> 2;          // 0..63
    const int lk4  = (tid & 3) << 2;    // 0,4,8,12

    const float* Ap0 = A + (size_t)(bm + lrow) * K + lk4;
    const float* Ap1 = Ap0 + (size_t)64 * K;
    const float* Wp0 = W + (size_t)(bn + lrow) * K + lk4;
    const float* Wp1 = Wp0 + (size_t)64 * K;

    float dtv = 0.f;
    if (TRANS == 2 || EPI == 2) dtv = *dtp;

    float c[4][4][4];
#pragma unroll
    for (int mi = 0; mi < 4; mi++)
#pragma unroll
        for (int ni = 0; ni < 4; ni++)
#pragma unroll
            for (int j = 0; j < 4; j++) c[mi][ni][j] = 0.f;

    float4 a0, a1, w0, w1;

    // ---- transform helper applied at staging time (fp32, then tf32 round) ----
    auto xform = [&](float4 v, int kbase) -> float4 {
        if (TRANS == 1) {
            float4 sc = *(const float4*)(scl + kbase + lk4);
            float4 sf = *(const float4*)(shf + kbase + lk4);
            v.x = fmaxf(fmaf(v.x, sc.x, sf.x), 0.f);
            v.y = fmaxf(fmaf(v.y, sc.y, sf.y), 0.f);
            v.z = fmaxf(fmaf(v.z, sc.z, sf.z), 0.f);
            v.w = fmaxf(fmaf(v.w, sc.w, sf.w), 0.f);
        }
        if (TRANS == 2) { v.x *= dtv; v.y *= dtv; v.z *= dtv; v.w *= dtv; }
        return v;
    };

    // ---- load k=0 tile and stage into buffer 0 ----
    a0 = xform(*(const float4*)(Ap0), 0);
    a1 = xform(*(const float4*)(Ap1), 0);
    w0 = *(const float4*)(Wp0);
    w1 = *(const float4*)(Wp1);
    *(uint4*)&As[0][lrow     ][lk4] = cvt4(a0);
    *(uint4*)&As[0][lrow + 64][lk4] = cvt4(a1);
    *(uint4*)&Bs[0][lrow     ][lk4] = cvt4(w0);
    *(uint4*)&Bs[0][lrow + 64][lk4] = cvt4(w1);
    __syncthreads();

    int buf = 0;
    for (int k0 = 0; k0 < K; k0 += BK) {
        const int kn = k0 + BK;
        // prefetch next tile into registers
        if (kn < K) {
            a0 = xform(*(const float4*)(Ap0 + kn), kn);
            a1 = xform(*(const float4*)(Ap1 + kn), kn);
            w0 = *(const float4*)(Wp0 + kn);
            w1 = *(const float4*)(Wp1 + kn);
        }

        // compute current tile: 2 k-steps of 8
#pragma unroll
        for (int ks = 0; ks < 2; ks++) {
            const int kk = ks * 8;
            uint32_t af[4][4], bf[4][2];
#pragma unroll
            for (int mi = 0; mi < 4; mi++) {
                const int r0 = wm * 64 + mi * 16 + grp;
                af[mi][0] = As[buf][r0    ][kk + qk];
                af[mi][1] = As[buf][r0 + 8][kk + qk];
                af[mi][2] = As[buf][r0    ][kk + qk + 4];
                af[mi][3] = As[buf][r0 + 8][kk + qk + 4];
            }
#pragma unroll
            for (int ni = 0; ni < 4; ni++) {
                const int cn = wn * 32 + ni * 8 + grp;
                bf[ni][0] = Bs[buf][cn][kk + qk];
                bf[ni][1] = Bs[buf][cn][kk + qk + 4];
            }
#pragma unroll
            for (int mi = 0; mi < 4; mi++)
#pragma unroll
                for (int ni = 0; ni < 4; ni++)
                    mma_tf32(c[mi][ni], af[mi], bf[ni]);
        }

        // stage next tile; single barrier per iteration
        if (kn < K) {
            const int nb = buf ^ 1;
            *(uint4*)&As[nb][lrow     ][lk4] = cvt4(a0);
            *(uint4*)&As[nb][lrow + 64][lk4] = cvt4(a1);
            *(uint4*)&Bs[nb][lrow     ][lk4] = cvt4(w0);
            *(uint4*)&Bs[nb][lrow + 64][lk4] = cvt4(w1);
            __syncthreads();
            buf = nb;
        }
    }

    // ---- epilogue ----
    float hh = 0.f, sqh = 0.f;
    if (EPI == 2) {
        hh  = dtv * (1.f / (float)NSTEPS);
        sqh = sqrtf(fabsf(hh) + 1e-8f);
    }

#pragma unroll
    for (int mi = 0; mi < 4; mi++) {
#pragma unroll
        for (int ni = 0; ni < 4; ni++) {
            const int r0 = bm + wm * 64 + mi * 16 + grp;
            const int cn = bn + wn * 32 + ni * 8 + (qk << 1);
            float2 bias2 = make_float2(0.f, 0.f);
            if (EPI != 3) bias2 = *(const float2*)(bias + cn);
#pragma unroll
            for (int h = 0; h < 2; h++) {
                const int r = r0 + h * 8;
                const size_t off = (size_t)r * N + cn;
                float vx = c[mi][ni][2 * h]     + bias2.x;
                float vy = c[mi][ni][2 * h + 1] + bias2.y;
                if (EPI == 0) {
                    *(float2*)(Cout + off) = make_float2(vx, vy);
                } else if (EPI == 1) {
                    *(float2*)(Cout + off) = make_float2(tanhf(vx), tanhf(vy));
                } else if (EPI == 2) {
                    float2 zf = *(const float2*)(zb + off);
                    float2 ff = *(const float2*)(Fb + off);
                    float2 ef = *(const float2*)(Eb + off);
                    float gx = softplus_f(vx) + 1e-5f;
                    float gy = softplus_f(vy) + 1e-5f;
                    zf.x = zf.x + hh * ff.x + sqh * gx * ef.x;
                    zf.y = zf.y + hh * ff.y + sqh * gy * ef.y;
                    *(float2*)(zb + off) = zf;
                } else { // EPI == 3
                    float2 zf = *(const float2*)(zb + off);
                    zf.x += c[mi][ni][2 * h];
                    zf.y += c[mi][ni][2 * h + 1];
                    *(float2*)(zb + off)   = zf;
                    *(float2*)(dout + off) = zf;
                }
            }
        }
    }
}

// ---------------------------------------------------------------------------
// BN batch statistics (deterministic two-phase column reduction, H = 1024)
// ---------------------------------------------------------------------------
__global__ void bnstat_part(const float* __restrict__ X)
{
    __shared__ float sm1[256], sm2[256];
    const int tid = threadIdx.x;
    const int tx = tid & 31, r0 = tid >> 5;
    const int col = blockIdx.x * 32 + tx;
    const int rowbase = blockIdx.y * 64;
    float s = 0.f, s2 = 0.f;
#pragma unroll
    for (int i = 0; i < 8; i++) {
        float v = X[(size_t)(rowbase + i * 8 + r0) * HDIM + col];
        s += v;
        s2 = fmaf(v, v, s2);
    }
    sm1[tid] = s; sm2[tid] = s2;
    __syncthreads();
    if (tid < 32) {
        float a = 0.f, b = 0.f;
#pragma unroll
        for (int r = 0; r < 8; r++) { a += sm1[r * 32 + tid]; b += sm2[r * 32 + tid]; }
        g_psum [blockIdx.y * HDIM + blockIdx.x * 32 + tid] = a;
        g_psum2[blockIdx.y * HDIM + blockIdx.x * 32 + tid] = b;
    }
}

// grid = HDIM/64 = 16 blocks, block = 256: 64 cols x 4 row-threads, coalesced
__global__ void bnstat_final(const float* __restrict__ g, const float* __restrict__ be)
{
    __shared__ float sm1[256], sm2[256];
    const int tid = threadIdx.x;
    const int cl  = tid & 63;
    const int r0  = tid >> 6;    // 0..3
    const int c   = blockIdx.x * 64 + cl;
    float s = 0.f, s2 = 0.f;
#pragma unroll
    for (int r = r0; r < 64; r += 4) {
        s  += g_psum [r * HDIM + c];
        s2 += g_psum2[r * HDIM + c];
    }
    sm1[tid] = s; sm2[tid] = s2;
    __syncthreads();
    if (tid < 64) {
        s  = sm1[tid] + sm1[tid + 64] + sm1[tid + 128] + sm1[tid + 192];
        s2 = sm2[tid] + sm2[tid + 64] + sm2[tid + 128] + sm2[tid + 192];
        const float mu  = s * (1.f / (float)BATCH);
        const float var = fmaf(-mu, mu, s2 * (1.f / (float)BATCH));
        const int cc = blockIdx.x * 64 + tid;
        const float sc = g[cc] / sqrtf(var + 1e-5f);
        g_scale[cc] = sc;
        g_shift[cc] = fmaf(-mu, sc, be[cc]);
    }
}

// ---------------------------------------------------------------------------
__global__ void copy_k(const float* __restrict__ s, float* __restrict__ d, int n4)
{
    for (int i = blockIdx.x * blockDim.x + threadIdx.x; i < n4; i += gridDim.x * blockDim.x)
        ((float4*)d)[i] = ((const float4*)s)[i];
}

// yt = z_next @ C^T + (ut*dt) @ D^T   -> out[4096*512 + r*25 + n]  (fp32 exact path)
__global__ void yt_k(const float* __restrict__ ut, const float* __restrict__ Cm,
                     const float* __restrict__ Dm, const float* __restrict__ dtp,
                     float* __restrict__ out)
{
    const int i = blockIdx.x * blockDim.x + threadIdx.x;
    if (i >= BATCH * 25) return;
    const int r = i / 25;
    const int n = i - r * 25;

    const float4* zr = (const float4*)(g_zbuf + (size_t)r * DDIM);
    const float4* cr = (const float4*)(Cm + (size_t)n * DDIM);
    float acc = 0.f;
#pragma unroll 8
    for (int k = 0; k < DDIM / 4; k++) {
        float4 a = zr[k], b = cr[k];
        acc += a.x * b.x + a.y * b.y + a.z * b.z + a.w * b.w;
    }
    const float4* ur = (const float4*)(ut + (size_t)r * 64);
    const float4* dr = (const float4*)(Dm + (size_t)n * 64);
    float acc2 = 0.f;
#pragma unroll
    for (int k = 0; k < 16; k++) {
        float4 a = ur[k], b = dr[k];
        acc2 += a.x * b.x + a.y * b.y + a.z * b.z + a.w * b.w;
    }
    out[(size_t)BATCH * DDIM + i] = acc + (*dtp) * acc2;
}

// ===========================================================================
extern "C" void kernel_launch(void* const* d_in, const int* in_sizes, int n_in,
                              void* d_out, int out_size)
{
    (void)in_sizes; (void)n_in; (void)out_size;

    const float* z_dyn = (const float*)d_in[0];
    /* d_in[1] = z_static : unused by reference */
    const float* dtp   = (const float*)d_in[2];
    const float* ut    = (const float*)d_in[3];
    const float* eps   = (const float*)d_in[4];
    const float* W1  = (const float*)d_in[5];
    const float* b1  = (const float*)d_in[6];
    const float* g1  = (const float*)d_in[7];
    const float* be1 = (const float*)d_in[8];
    const float* W2  = (const float*)d_in[9];
    const float* b2  = (const float*)d_in[10];
    const float* g2  = (const float*)d_in[11];
    const float* be2 = (const float*)d_in[12];
    const float* W3  = (const float*)d_in[13];
    const float* b3  = (const float*)d_in[14];
    const float* Wd1 = (const float*)d_in[15];
    const float* bd1 = (const float*)d_in[16];
    const float* Wd2 = (const float*)d_in[17];
    const float* bd2 = (const float*)d_in[18];
    const float* Bs  = (const float*)d_in[19];
    const float* Cm  = (const float*)d_in[20];
    const float* Dm  = (const float*)d_in[21];
    float* out = (float*)d_out;

    float *zbuf, *A1, *A2, *F, *T, *scl, *shf;
    cudaGetSymbolAddress((void**)&zbuf, g_zbuf);
    cudaGetSymbolAddress((void**)&A1,   g_A1);
    cudaGetSymbolAddress((void**)&A2,   g_A2);
    cudaGetSymbolAddress((void**)&F,    g_F);
    cudaGetSymbolAddress((void**)&T,    g_T);
    cudaGetSymbolAddress((void**)&scl,  g_scale);
    cudaGetSymbolAddress((void**)&shf,  g_shift);

    const dim3 blk(256);
    const dim3 gridH(HDIM / BN, BATCH / BM);  // (8, 32)  N=1024
    const dim3 gridD(DDIM / BN, BATCH / BM);  // (4, 32)  N=512
    const dim3 gridS(HDIM / 32, 64);          // BN stats phase 1

    copy_k<<<512, 256>>>(z_dyn, zbuf, BATCH * DDIM / 4);

    for (int s = 0; s < NSTEPS; s++) {
        const float* eps_s = eps + (size_t)s * BATCH * DDIM;

        // drift layer 1
        gemm_tc<0, 0><<<gridH, blk>>>(zbuf, W1, b1, A1, BATCH, HDIM, DDIM,
                                      nullptr, nullptr, nullptr, nullptr, nullptr, nullptr, nullptr);
        bnstat_part<<<gridS, 256>>>(A1);
        bnstat_final<<<HDIM / 64, 256>>>(g1, be1);
        // drift layer 2 (BN1+ReLU fused into A staging)
        gemm_tc<1, 0><<<gridH, blk>>>(A1, W2, b2, A2, BATCH, HDIM, HDIM,
                                      scl, shf, nullptr, nullptr, nullptr, nullptr, nullptr);
        bnstat_part<<<gridS, 256>>>(A2);
        bnstat_final<<<HDIM / 64, 256>>>(g2, be2);
        // drift layer 3 (BN2+ReLU fused into A staging)
        gemm_tc<1, 0><<<gridD, blk>>>(A2, W3, b3, F, BATCH, DDIM, HDIM,
                                      scl, shf, nullptr, nullptr, nullptr, nullptr, nullptr);
        // diffusion layer 1 (tanh epilogue)
        gemm_tc<0, 1><<<gridD, blk>>>(zbuf, Wd1, bd1, T, BATCH, DDIM, DDIM,
                                      nullptr, nullptr, nullptr, nullptr, nullptr, nullptr, nullptr);
        // diffusion layer 2 + Euler-Maruyama update (softplus epilogue, in-place z)
        gemm_tc<0, 2><<<gridD, blk>>>(T, Wd2, bd2, nullptr, BATCH, DDIM, DDIM,
                                      nullptr, nullptr, dtp, F, eps_s, zbuf, nullptr);
    }

    // z_next = z + (ut*dt) @ B_sde^T  -> zbuf and out[0 : 4096*512)
    gemm_tc<2, 3><<<gridD, blk>>>(ut, Bs, nullptr, nullptr, BATCH, DDIM, 64,
                                  nullptr, nullptr, dtp, nullptr, nullptr, zbuf, out);
    // yt -> out[4096*512 : +4096*25)
    yt_k<<<(BATCH * 25 + 255) / 256, 256>>>(ut, Cm, Dm, dtp, out);
}

// round 6
// speedup vs baseline: 3.8032x; 1.1011x over previous
#include <cuda_runtime.h>
#include <cstdint>
#include <math.h>

// ============================================================================
// ConditionedLatentSDETransition — tf32 tensor-core pipeline, round 6
//   * cp.async (LDGSTS) smem staging, raw-fp32 tf32 MMA (no cvt)
//   * BN partial statistics fused into GEMM epilogue (bnstat_part eliminated)
//   * no initial copy; dt-scale folded into final epilogue
// ============================================================================

#define BM 128
#define BN 128
#define BK 16
#define KS_LD 20    // BK + 4 pad; (20*grp + qk) mod 32 all-distinct -> conflict-free

#define BATCH 4096
#define DDIM  512
#define HDIM  1024
#define NSTEPS 8

// ---- scratch (device globals; no allocation allowed) ----
__device__ float g_zbuf[BATCH * DDIM];
__device__ float g_A1[BATCH * HDIM];
__device__ float g_A2[BATCH * HDIM];
__device__ float g_F[BATCH * DDIM];
__device__ float g_T[BATCH * DDIM];
__device__ float g_psum [64 * HDIM];
__device__ float g_psum2[64 * HDIM];
__device__ float g_scale[HDIM];
__device__ float g_shift[HDIM];

__device__ __forceinline__ float softplus_f(float x) {
    return fmaxf(x, 0.f) + log1pf(expf(-fabsf(x)));   // jax.nn.softplus
}

__device__ __forceinline__ void cp16(float* sdst, const float* gsrc) {
    uint32_t sa = (uint32_t)__cvta_generic_to_shared(sdst);
    asm volatile("cp.async.cg.shared.global [%0], [%1], 16;" :: "r"(sa), "l"(gsrc));
}
__device__ __forceinline__ void cp_commit() { asm volatile("cp.async.commit_group;"); }
__device__ __forceinline__ void cp_wait0()  { asm volatile("cp.async.wait_group 0;"); }

__device__ __forceinline__ void mma_tf32(float* c, const uint32_t* a, const uint32_t* b) {
    asm volatile(
        "mma.sync.aligned.m16n8k8.row.col.f32.tf32.tf32.f32 "
        "{%0,%1,%2,%3}, {%4,%5,%6,%7}, {%8,%9}, {%0,%1,%2,%3};\n"
        : "+f"(c[0]), "+f"(c[1]), "+f"(c[2]), "+f"(c[3])
        : "r"(a[0]), "r"(a[1]), "r"(a[2]), "r"(a[3]), "r"(b[0]), "r"(b[1]));
}

// ---------------------------------------------------------------------------
// Tensor-core GEMM:  C[M,N] = transform(A)[M,K] @ W[N,K]^T  (+ bias, epilogue)
// TRANS: 0 = none (cp.async A path), 1 = BN(scale,shift)+ReLU (register A path)
// EPI:   0 = store acc+bias
//        1 = store tanh(acc+bias)
//        2 = g = softplus(acc+bias)+1e-5;  zout = zin + h*Fb + sqrt_h*g*Eb
//        3 = val = zin + dt*acc; zout = val; dout = val       (final z_next)
// BNS:   1 = also emit per-CTA BN partial sums/squares into g_psum/g_psum2
// CTA 128x128x16, 8 warps (warp tile 64x32), cp.async double-buffered.
// ---------------------------------------------------------------------------
template<int TRANS, int EPI, int BNS>
__global__ __launch_bounds__(256, 2)
void gemm_tc(const float* __restrict__ A, const float* __restrict__ W,
             const float* __restrict__ bias, float* __restrict__ Cout,
             int M, int N, int K,
             const float* __restrict__ scl, const float* __restrict__ shf,
             const float* __restrict__ dtp,
             const float* __restrict__ Fb, const float* __restrict__ Eb,
             const float* __restrict__ zin, float* __restrict__ zout,
             float* __restrict__ dout)
{
    __shared__ float As[2][BM][KS_LD];
    __shared__ float Bs[2][BN][KS_LD];

    const int tid  = threadIdx.x;
    const int lane = tid & 31;
    const int wid  = tid >> 5;
    const int wm   = wid >> 2;          // 0..1  -> M offset wm*64
    const int wn   = wid & 3;           // 0..3  -> N offset wn*32
    const int grp  = lane >> 2;         // 0..7
    const int qk   = lane & 3;          // 0..3
    const int bm   = blockIdx.y * BM;
    const int bn   = blockIdx.x * BN;

    const int lrow = tid >> 2;          // 0..63
    const int lk4  = (tid & 3) << 2;    // 0,4,8,12

    const float* Ap0 = A + (size_t)(bm + lrow) * K + lk4;
    const float* Ap1 = Ap0 + (size_t)64 * K;
    const float* Wp0 = W + (size_t)(bn + lrow) * K + lk4;
    const float* Wp1 = Wp0 + (size_t)64 * K;

    float dtv = 0.f;
    if (EPI == 2 || EPI == 3) dtv = *dtp;

    float c[4][4][4];
#pragma unroll
    for (int mi = 0; mi < 4; mi++)
#pragma unroll
        for (int ni = 0; ni < 4; ni++)
#pragma unroll
            for (int j = 0; j < 4; j++) c[mi][ni][j] = 0.f;

    // fp32 BN+ReLU transform applied pre-staging (register path, TRANS==1)
    auto xform = [&](float4 v, int kbase) -> float4 {
        float4 sc = *(const float4*)(scl + kbase + lk4);
        float4 sf = *(const float4*)(shf + kbase + lk4);
        v.x = fmaxf(fmaf(v.x, sc.x, sf.x), 0.f);
        v.y = fmaxf(fmaf(v.y, sc.y, sf.y), 0.f);
        v.z = fmaxf(fmaf(v.z, sc.z, sf.z), 0.f);
        v.w = fmaxf(fmaf(v.w, sc.w, sf.w), 0.f);
        return v;
    };

    // ---- prologue: stage tile k=0 into buffer 0 ----
    if (TRANS == 1) {
        float4 a0 = xform(*(const float4*)(Ap0), 0);
        float4 a1 = xform(*(const float4*)(Ap1), 0);
        *(float4*)&As[0][lrow     ][lk4] = a0;
        *(float4*)&As[0][lrow + 64][lk4] = a1;
    } else {
        cp16(&As[0][lrow     ][lk4], Ap0);
        cp16(&As[0][lrow + 64][lk4], Ap1);
    }
    cp16(&Bs[0][lrow     ][lk4], Wp0);
    cp16(&Bs[0][lrow + 64][lk4], Wp1);
    cp_commit();
    cp_wait0();
    __syncthreads();

    int buf = 0;
    for (int k0 = 0; k0 < K; k0 += BK) {
        const int kn = k0 + BK;
        const int nb = buf ^ 1;
        float4 a0, a1;
        if (kn < K) {
            if (TRANS == 1) {
                a0 = xform(*(const float4*)(Ap0 + kn), kn);
                a1 = xform(*(const float4*)(Ap1 + kn), kn);
            } else {
                cp16(&As[nb][lrow     ][lk4], Ap0 + kn);
                cp16(&As[nb][lrow + 64][lk4], Ap1 + kn);
            }
            cp16(&Bs[nb][lrow     ][lk4], Wp0 + kn);
            cp16(&Bs[nb][lrow + 64][lk4], Wp1 + kn);
            cp_commit();
        }

        // compute current tile: 2 k-steps of 8
#pragma unroll
        for (int ks = 0; ks < 2; ks++) {
            const int kk = ks * 8;
            uint32_t af[4][4], bf[4][2];
#pragma unroll
            for (int mi = 0; mi < 4; mi++) {
                const int r0 = wm * 64 + mi * 16 + grp;
                af[mi][0] = *(const uint32_t*)&As[buf][r0    ][kk + qk];
                af[mi][1] = *(const uint32_t*)&As[buf][r0 + 8][kk + qk];
                af[mi][2] = *(const uint32_t*)&As[buf][r0    ][kk + qk + 4];
                af[mi][3] = *(const uint32_t*)&As[buf][r0 + 8][kk + qk + 4];
            }
#pragma unroll
            for (int ni = 0; ni < 4; ni++) {
                const int cn = wn * 32 + ni * 8 + grp;
                bf[ni][0] = *(const uint32_t*)&Bs[buf][cn][kk + qk];
                bf[ni][1] = *(const uint32_t*)&Bs[buf][cn][kk + qk + 4];
            }
#pragma unroll
            for (int mi = 0; mi < 4; mi++)
#pragma unroll
                for (int ni = 0; ni < 4; ni++)
                    mma_tf32(c[mi][ni], af[mi], bf[ni]);
        }

        if (kn < K) {
            if (TRANS == 1) {
                *(float4*)&As[nb][lrow     ][lk4] = a0;
                *(float4*)&As[nb][lrow + 64][lk4] = a1;
            }
            cp_wait0();
            __syncthreads();
            buf = nb;
        }
    }

    // ---- epilogue ----
    float hh = 0.f, sqh = 0.f;
    if (EPI == 2) {
        hh  = dtv * (1.f / (float)NSTEPS);
        sqh = sqrtf(fabsf(hh) + 1e-8f);
    }

    float s1x[4], s1y[4], s2x[4], s2y[4];
    if (BNS) {
#pragma unroll
        for (int ni = 0; ni < 4; ni++) { s1x[ni] = 0.f; s1y[ni] = 0.f; s2x[ni] = 0.f; s2y[ni] = 0.f; }
    }

#pragma unroll
    for (int mi = 0; mi < 4; mi++) {
#pragma unroll
        for (int ni = 0; ni < 4; ni++) {
            const int r0 = bm + wm * 64 + mi * 16 + grp;
            const int cn = bn + wn * 32 + ni * 8 + (qk << 1);
            float2 bias2 = make_float2(0.f, 0.f);
            if (EPI != 3) bias2 = *(const float2*)(bias + cn);
#pragma unroll
            for (int h = 0; h < 2; h++) {
                const int r = r0 + h * 8;
                const size_t off = (size_t)r * N + cn;
                float vx = c[mi][ni][2 * h]     + bias2.x;
                float vy = c[mi][ni][2 * h + 1] + bias2.y;
                if (EPI == 0) {
                    *(float2*)(Cout + off) = make_float2(vx, vy);
                    if (BNS) {
                        s1x[ni] += vx; s2x[ni] = fmaf(vx, vx, s2x[ni]);
                        s1y[ni] += vy; s2y[ni] = fmaf(vy, vy, s2y[ni]);
                    }
                } else if (EPI == 1) {
                    *(float2*)(Cout + off) = make_float2(tanhf(vx), tanhf(vy));
                } else if (EPI == 2) {
                    float2 zf = *(const float2*)(zin + off);
                    float2 ff = *(const float2*)(Fb + off);
                    float2 ef = *(const float2*)(Eb + off);
                    float gx = softplus_f(vx) + 1e-5f;
                    float gy = softplus_f(vy) + 1e-5f;
                    zf.x = zf.x + hh * ff.x + sqh * gx * ef.x;
                    zf.y = zf.y + hh * ff.y + sqh * gy * ef.y;
                    *(float2*)(zout + off) = zf;
                } else { // EPI == 3
                    float2 zf = *(const float2*)(zin + off);
                    zf.x = fmaf(dtv, c[mi][ni][2 * h],     zf.x);
                    zf.y = fmaf(dtv, c[mi][ni][2 * h + 1], zf.y);
                    *(float2*)(zout + off) = zf;
                    *(float2*)(dout + off) = zf;
                }
            }
        }
    }

    // ---- fused BN partial stats: per-CTA column sums over 64 rows (per wm) ----
    if (BNS) {
        const int slot = blockIdx.y * 2 + wm;   // 0..63
#pragma unroll
        for (int ni = 0; ni < 4; ni++) {
            float a = s1x[ni], b = s1y[ni], p = s2x[ni], q = s2y[ni];
#pragma unroll
            for (int m = 4; m <= 16; m <<= 1) {
                a += __shfl_xor_sync(0xffffffffu, a, m);
                b += __shfl_xor_sync(0xffffffffu, b, m);
                p += __shfl_xor_sync(0xffffffffu, p, m);
                q += __shfl_xor_sync(0xffffffffu, q, m);
            }
            if (lane < 4) {   // grp == 0 lanes hold the 64-row totals
                const int cn = bn + wn * 32 + ni * 8 + (qk << 1);
                *(float2*)&g_psum [slot * HDIM + cn] = make_float2(a, b);
                *(float2*)&g_psum2[slot * HDIM + cn] = make_float2(p, q);
            }
        }
    }
}

// ---------------------------------------------------------------------------
// BN final reduce: grid = HDIM/64 blocks, block = 256 (64 cols x 4 row-threads)
// ---------------------------------------------------------------------------
__global__ void bnstat_final(const float* __restrict__ g, const float* __restrict__ be)
{
    __shared__ float sm1[256], sm2[256];
    const int tid = threadIdx.x;
    const int cl  = tid & 63;
    const int r0  = tid >> 6;    // 0..3
    const int c   = blockIdx.x * 64 + cl;
    float s = 0.f, s2 = 0.f;
#pragma unroll
    for (int r = r0; r < 64; r += 4) {
        s  += g_psum [r * HDIM + c];
        s2 += g_psum2[r * HDIM + c];
    }
    sm1[tid] = s; sm2[tid] = s2;
    __syncthreads();
    if (tid < 64) {
        s  = sm1[tid] + sm1[tid + 64] + sm1[tid + 128] + sm1[tid + 192];
        s2 = sm2[tid] + sm2[tid + 64] + sm2[tid + 128] + sm2[tid + 192];
        const float mu  = s * (1.f / (float)BATCH);
        const float var = fmaf(-mu, mu, s2 * (1.f / (float)BATCH));
        const int cc = blockIdx.x * 64 + tid;
        const float sc = g[cc] / sqrtf(var + 1e-5f);
        g_scale[cc] = sc;
        g_shift[cc] = fmaf(-mu, sc, be[cc]);
    }
}

// yt = z_next @ C^T + (ut*dt) @ D^T   -> out[4096*512 + r*25 + n]  (fp32 exact)
__global__ void yt_k(const float* __restrict__ ut, const float* __restrict__ Cm,
                     const float* __restrict__ Dm, const float* __restrict__ dtp,
                     float* __restrict__ out)
{
    const int i = blockIdx.x * blockDim.x + threadIdx.x;
    if (i >= BATCH * 25) return;
    const int r = i / 25;
    const int n = i - r * 25;

    const float4* zr = (const float4*)(g_zbuf + (size_t)r * DDIM);
    const float4* cr = (const float4*)(Cm + (size_t)n * DDIM);
    float acc = 0.f;
#pragma unroll 8
    for (int k = 0; k < DDIM / 4; k++) {
        float4 a = zr[k], b = cr[k];
        acc += a.x * b.x + a.y * b.y + a.z * b.z + a.w * b.w;
    }
    const float4* ur = (const float4*)(ut + (size_t)r * 64);
    const float4* dr = (const float4*)(Dm + (size_t)n * 64);
    float acc2 = 0.f;
#pragma unroll
    for (int k = 0; k < 16; k++) {
        float4 a = ur[k], b = dr[k];
        acc2 += a.x * b.x + a.y * b.y + a.z * b.z + a.w * b.w;
    }
    out[(size_t)BATCH * DDIM + i] = acc + (*dtp) * acc2;
}

// ===========================================================================
extern "C" void kernel_launch(void* const* d_in, const int* in_sizes, int n_in,
                              void* d_out, int out_size)
{
    (void)in_sizes; (void)n_in; (void)out_size;

    const float* z_dyn = (const float*)d_in[0];
    /* d_in[1] = z_static : unused by reference */
    const float* dtp   = (const float*)d_in[2];
    const float* ut    = (const float*)d_in[3];
    const float* eps   = (const float*)d_in[4];
    const float* W1  = (const float*)d_in[5];
    const float* b1  = (const float*)d_in[6];
    const float* g1  = (const float*)d_in[7];
    const float* be1 = (const float*)d_in[8];
    const float* W2  = (const float*)d_in[9];
    const float* b2  = (const float*)d_in[10];
    const float* g2  = (const float*)d_in[11];
    const float* be2 = (const float*)d_in[12];
    const float* W3  = (const float*)d_in[13];
    const float* b3  = (const float*)d_in[14];
    const float* Wd1 = (const float*)d_in[15];
    const float* bd1 = (const float*)d_in[16];
    const float* Wd2 = (const float*)d_in[17];
    const float* bd2 = (const float*)d_in[18];
    const float* Bsde= (const float*)d_in[19];
    const float* Cm  = (const float*)d_in[20];
    const float* Dm  = (const float*)d_in[21];
    float* out = (float*)d_out;

    float *zbuf, *A1, *A2, *F, *T, *scl, *shf;
    cudaGetSymbolAddress((void**)&zbuf, g_zbuf);
    cudaGetSymbolAddress((void**)&A1,   g_A1);
    cudaGetSymbolAddress((void**)&A2,   g_A2);
    cudaGetSymbolAddress((void**)&F,    g_F);
    cudaGetSymbolAddress((void**)&T,    g_T);
    cudaGetSymbolAddress((void**)&scl,  g_scale);
    cudaGetSymbolAddress((void**)&shf,  g_shift);

    const dim3 blk(256);
    const dim3 gridH(HDIM / BN, BATCH / BM);  // (8, 32)  N=1024
    const dim3 gridD(DDIM / BN, BATCH / BM);  // (4, 32)  N=512

    for (int s = 0; s < NSTEPS; s++) {
        const float* eps_s = eps + (size_t)s * BATCH * DDIM;
        const float* zsrc  = (s == 0) ? z_dyn : zbuf;

        // drift layer 1 (+ fused BN1 partial stats)
        gemm_tc<0, 0, 1><<<gridH, blk>>>(zsrc, W1, b1, A1, BATCH, HDIM, DDIM,
                                         nullptr, nullptr, nullptr, nullptr, nullptr,
                                         nullptr, nullptr, nullptr);
        bnstat_final<<<HDIM / 64, 256>>>(g1, be1);
        // drift layer 2 (BN1+ReLU fused into A staging; + fused BN2 partial stats)
        gemm_tc<1, 0, 1><<<gridH, blk>>>(A1, W2, b2, A2, BATCH, HDIM, HDIM,
                                         scl, shf, nullptr, nullptr, nullptr,
                                         nullptr, nullptr, nullptr);
        bnstat_final<<<HDIM / 64, 256>>>(g2, be2);
        // drift layer 3 (BN2+ReLU fused into A staging)
        gemm_tc<1, 0, 0><<<gridD, blk>>>(A2, W3, b3, F, BATCH, DDIM, HDIM,
                                         scl, shf, nullptr, nullptr, nullptr,
                                         nullptr, nullptr, nullptr);
        // diffusion layer 1 (tanh epilogue)
        gemm_tc<0, 1, 0><<<gridD, blk>>>(zsrc, Wd1, bd1, T, BATCH, DDIM, DDIM,
                                         nullptr, nullptr, nullptr, nullptr, nullptr,
                                         nullptr, nullptr, nullptr);
        // diffusion layer 2 + Euler-Maruyama update (zin -> zout)
        gemm_tc<0, 2, 0><<<gridD, blk>>>(T, Wd2, bd2, nullptr, BATCH, DDIM, DDIM,
                                         nullptr, nullptr, dtp, F, eps_s,
                                         zsrc, zbuf, nullptr);
    }

    // z_next = z + dt*(ut @ B_sde^T) -> zbuf and out[0 : 4096*512)
    gemm_tc<0, 3, 0><<<gridD, blk>>>(ut, Bsde, nullptr, nullptr, BATCH, DDIM, 64,
                                     nullptr, nullptr, dtp, nullptr, nullptr,
                                     zbuf, zbuf, out);
    // yt -> out[4096*512 : +4096*25)
    yt_k<<<(BATCH * 25 + 255) / 256, 256>>>(ut, Cm, Dm, dtp, out);
}

// round 8
// speedup vs baseline: 6.3566x; 1.6714x over previous
#include <cuda_runtime.h>
#include <cuda_fp16.h>
#include <cstdint>
#include <math.h>

// ============================================================================
// ConditionedLatentSDETransition — fp16 tensor-core (mma.m16n8k16 + ldmatrix)
//   * all GEMM operands fp16 (fp32 accumulate, fp32 z-state, fp32 BN stats)
//   * weights/ut/z converted to fp16 once per launch; activations written fp16
//     directly from GEMM epilogues
//   * cp.async staging; BN+ReLU fused in register staging path
//   * BN partial stats fused into GEMM epilogues; single small final reduce
// ============================================================================

#define BM 128
#define BN 128
#define BK 32
#define KS_LD 40    // BK + 8 pad halves; row stride 80B = 5 granules -> ldmatrix conflict-free

#define BATCH 4096
#define DDIM  512
#define HDIM  1024
#define NSTEPS 8

// ---- scratch (device globals; no allocation allowed) ----
__device__ float  g_zbuf[BATCH * DDIM];           // fp32 z master
__device__ float  g_F[BATCH * DDIM];              // drift output (fp32, epilogue-only use)
__device__ float  g_psum [64 * HDIM];
__device__ float  g_psum2[64 * HDIM];
__device__ float  g_scale[HDIM];
__device__ float  g_shift[HDIM];

__device__ __half g_zh [BATCH * DDIM];            // fp16 shadow of z
__device__ __half g_A1h[BATCH * HDIM];
__device__ __half g_A2h[BATCH * HDIM];
__device__ __half g_Th [BATCH * DDIM];
__device__ __half g_W1h [HDIM * DDIM];
__device__ __half g_W2h [HDIM * HDIM];
__device__ __half g_W3h [DDIM * HDIM];
__device__ __half g_Wd1h[DDIM * DDIM];
__device__ __half g_Wd2h[DDIM * DDIM];
__device__ __half g_Bsh [DDIM * 64];
__device__ __half g_uth [BATCH * 64];

__device__ __forceinline__ float softplus_f(float x) {
    return fmaxf(x, 0.f) + log1pf(expf(-fabsf(x)));   // jax.nn.softplus
}

__device__ __forceinline__ void cp16(void* sdst, const void* gsrc) {
    uint32_t sa = (uint32_t)__cvta_generic_to_shared(sdst);
    asm volatile("cp.async.cg.shared.global [%0], [%1], 16;" :: "r"(sa), "l"(gsrc));
}
__device__ __forceinline__ void cp_commit() { asm volatile("cp.async.commit_group;"); }
__device__ __forceinline__ void cp_wait0()  { asm volatile("cp.async.wait_group 0;"); }

__device__ __forceinline__ void ldsm4(uint32_t* r, const void* p) {
    uint32_t a = (uint32_t)__cvta_generic_to_shared(p);
    asm volatile("ldmatrix.sync.aligned.m8n8.x4.shared.b16 {%0,%1,%2,%3}, [%4];"
                 : "=r"(r[0]), "=r"(r[1]), "=r"(r[2]), "=r"(r[3]) : "r"(a));
}

__device__ __forceinline__ void mma_f16(float* c, const uint32_t* a, const uint32_t* b) {
    asm volatile(
        "mma.sync.aligned.m16n8k16.row.col.f32.f16.f16.f32 "
        "{%0,%1,%2,%3}, {%4,%5,%6,%7}, {%8,%9}, {%0,%1,%2,%3};\n"
        : "+f"(c[0]), "+f"(c[1]), "+f"(c[2]), "+f"(c[3])
        : "r"(a[0]), "r"(a[1]), "r"(a[2]), "r"(a[3]), "r"(b[0]), "r"(b[1]));
}

// ---------------------------------------------------------------------------
// fp16 tensor-core GEMM: C[M,N] = transform(A)[M,K] @ W[N,K]^T (+bias, epilogue)
// TRANS: 0 = cp.async A (raw fp16), 1 = BN(scale,shift)+ReLU in fp32 (register path)
// EPI:   0 = acc+bias store          (OUTH: 1 -> fp16 CoutH, 0 -> fp32 CoutF)
//        1 = tanh(acc+bias) store    (OUTH as above)
//        2 = g=softplus(acc+bias)+1e-5; zout = zin + h*Fb + sqrt_h*g*Eb; zhout=fp16(zout)
//        3 = val = zin + dt*acc; zout = val; dout = val
// BNS:   1 = emit per-CTA BN column partial sums into g_psum/g_psum2
// CTA 128x128x32, 8 warps (warp tile 64x32), double-buffered smem.
// ---------------------------------------------------------------------------
template<int TRANS, int EPI, int BNS, int OUTH>
__global__ __launch_bounds__(256, 2)
void gemm_h(const __half* __restrict__ Ah, const __half* __restrict__ Wh,
            const float* __restrict__ bias,
            float* __restrict__ CoutF, __half* __restrict__ CoutH,
            int M, int N, int K,
            const float* __restrict__ scl, const float* __restrict__ shf,
            const float* __restrict__ dtp,
            const float* __restrict__ Fb, const float* __restrict__ Eb,
            const float* __restrict__ zin, float* __restrict__ zout,
            __half* __restrict__ zhout, float* __restrict__ dout)
{
    __shared__ __half As[2][BM][KS_LD];
    __shared__ __half Bs[2][BN][KS_LD];

    const int tid  = threadIdx.x;
    const int lane = tid & 31;
    const int wid  = tid >> 5;
    const int wm   = wid >> 2;          // 0..1 -> M offset wm*64
    const int wn   = wid & 3;           // 0..3 -> N offset wn*32
    const int grp  = lane >> 2;         // 0..7
    const int qk   = lane & 3;          // 0..3
    const int bm   = blockIdx.y * BM;
    const int bn   = blockIdx.x * BN;

    const int row0 = tid >> 2;          // 0..63
    const int seg8 = (tid & 3) << 3;    // 0,8,16,24

    const __half* Ap0 = Ah + (size_t)(bm + row0) * K + seg8;
    const __half* Ap1 = Ap0 + (size_t)64 * K;
    const __half* Wp0 = Wh + (size_t)(bn + row0) * K + seg8;
    const __half* Wp1 = Wp0 + (size_t)64 * K;

    float dtv = 0.f;
    if (EPI == 2 || EPI == 3) dtv = *dtp;

    float c[4][4][4];
#pragma unroll
    for (int mi = 0; mi < 4; mi++)
#pragma unroll
        for (int ni = 0; ni < 4; ni++)
#pragma unroll
            for (int j = 0; j < 4; j++) c[mi][ni][j] = 0.f;

    // BN+ReLU transform of 8 halves (fp32 math), kb = absolute k of first half
    auto bn_tr = [&](uint4 raw, int kb) -> uint4 {
        __half2* h = (__half2*)&raw;
#pragma unroll
        for (int j = 0; j < 4; j++) {
            float2 f = __half22float2(h[j]);
            float scx = scl[kb + 2*j], scy = scl[kb + 2*j + 1];
            float sfx = shf[kb + 2*j], sfy = shf[kb + 2*j + 1];
            f.x = fmaxf(fmaf(f.x, scx, sfx), 0.f);
            f.y = fmaxf(fmaf(f.y, scy, sfy), 0.f);
            h[j] = __float22half2_rn(f);
        }
        return raw;
    };

    // ---- prologue: stage tile k=0 into buffer 0 ----
    if (TRANS == 1) {
        uint4 t0 = bn_tr(*(const uint4*)(Ap0), seg8);
        uint4 t1 = bn_tr(*(const uint4*)(Ap1), seg8);
        *(uint4*)&As[0][row0     ][seg8] = t0;
        *(uint4*)&As[0][row0 + 64][seg8] = t1;
    } else {
        cp16(&As[0][row0     ][seg8], Ap0);
        cp16(&As[0][row0 + 64][seg8], Ap1);
    }
    cp16(&Bs[0][row0     ][seg8], Wp0);
    cp16(&Bs[0][row0 + 64][seg8], Wp1);
    cp_commit();
    cp_wait0();
    __syncthreads();

    // precomputed ldmatrix row/col lane offsets
    const int a_r = lane & 15;             // row within 16
    const int a_k = (lane >> 4) << 3;      // 0 or 8
    const int b_r = (lane & 7) + ((lane >> 4) << 3);  // row within 16 (n)
    const int b_k = ((lane >> 3) & 1) << 3;           // 0 or 8

    int buf = 0;
    for (int k0 = 0; k0 < K; k0 += BK) {
        const int kn = k0 + BK;
        const int nb = buf ^ 1;
        uint4 t0, t1;
        if (kn < K) {
            if (TRANS == 1) {
                t0 = bn_tr(*(const uint4*)(Ap0 + kn), kn + seg8);
                t1 = bn_tr(*(const uint4*)(Ap1 + kn), kn + seg8);
            } else {
                cp16(&As[nb][row0     ][seg8], Ap0 + kn);
                cp16(&As[nb][row0 + 64][seg8], Ap1 + kn);
            }
            cp16(&Bs[nb][row0     ][seg8], Wp0 + kn);
            cp16(&Bs[nb][row0 + 64][seg8], Wp1 + kn);
            cp_commit();
        }

        // compute: 2 k-steps of 16
#pragma unroll
        for (int ks = 0; ks < 2; ks++) {
            const int kk = ks * 16;
            uint32_t af[4][4], bf[4][2];
#pragma unroll
            for (int mi = 0; mi < 4; mi++)
                ldsm4(af[mi], &As[buf][wm * 64 + mi * 16 + a_r][kk + a_k]);
#pragma unroll
            for (int nip = 0; nip < 2; nip++) {
                uint32_t t[4];
                ldsm4(t, &Bs[buf][wn * 32 + nip * 16 + b_r][kk + b_k]);
                bf[2 * nip][0] = t[0]; bf[2 * nip][1] = t[1];
                bf[2 * nip + 1][0] = t[2]; bf[2 * nip + 1][1] = t[3];
            }
#pragma unroll
            for (int mi = 0; mi < 4; mi++)
#pragma unroll
                for (int ni = 0; ni < 4; ni++)
                    mma_f16(c[mi][ni], af[mi], bf[ni]);
        }

        if (kn < K) {
            if (TRANS == 1) {
                *(uint4*)&As[nb][row0     ][seg8] = t0;
                *(uint4*)&As[nb][row0 + 64][seg8] = t1;
            }
            cp_wait0();
            __syncthreads();
            buf = nb;
        }
    }

    // ---- epilogue ----
    float hh = 0.f, sqh = 0.f;
    if (EPI == 2) {
        hh  = dtv * (1.f / (float)NSTEPS);
        sqh = sqrtf(fabsf(hh) + 1e-8f);
    }

    float s1x[4], s1y[4], s2x[4], s2y[4];
    if (BNS) {
#pragma unroll
        for (int ni = 0; ni < 4; ni++) { s1x[ni]=0.f; s1y[ni]=0.f; s2x[ni]=0.f; s2y[ni]=0.f; }
    }

#pragma unroll
    for (int mi = 0; mi < 4; mi++) {
#pragma unroll
        for (int ni = 0; ni < 4; ni++) {
            const int r0 = bm + wm * 64 + mi * 16 + grp;
            const int cn = bn + wn * 32 + ni * 8 + (qk << 1);
            float2 bias2 = make_float2(0.f, 0.f);
            if (EPI != 3) bias2 = *(const float2*)(bias + cn);
#pragma unroll
            for (int h = 0; h < 2; h++) {
                const int r = r0 + h * 8;
                const size_t off = (size_t)r * N + cn;
                float vx = c[mi][ni][2 * h]     + bias2.x;
                float vy = c[mi][ni][2 * h + 1] + bias2.y;
                if (EPI == 0) {
                    if (OUTH) *(__half2*)(CoutH + off) = __floats2half2_rn(vx, vy);
                    else      *(float2*)(CoutF + off)  = make_float2(vx, vy);
                    if (BNS) {
                        s1x[ni] += vx; s2x[ni] = fmaf(vx, vx, s2x[ni]);
                        s1y[ni] += vy; s2y[ni] = fmaf(vy, vy, s2y[ni]);
                    }
                } else if (EPI == 1) {
                    float tx = tanhf(vx), ty = tanhf(vy);
                    if (OUTH) *(__half2*)(CoutH + off) = __floats2half2_rn(tx, ty);
                    else      *(float2*)(CoutF + off)  = make_float2(tx, ty);
                } else if (EPI == 2) {
                    float2 zf = *(const float2*)(zin + off);
                    float2 ff = *(const float2*)(Fb + off);
                    float2 ef = *(const float2*)(Eb + off);
                    float gx = softplus_f(vx) + 1e-5f;
                    float gy = softplus_f(vy) + 1e-5f;
                    zf.x = zf.x + hh * ff.x + sqh * gx * ef.x;
                    zf.y = zf.y + hh * ff.y + sqh * gy * ef.y;
                    *(float2*)(zout + off) = zf;
                    *(__half2*)(zhout + off) = __floats2half2_rn(zf.x, zf.y);
                } else { // EPI == 3
                    float2 zf = *(const float2*)(zin + off);
                    zf.x = fmaf(dtv, c[mi][ni][2 * h],     zf.x);
                    zf.y = fmaf(dtv, c[mi][ni][2 * h + 1], zf.y);
                    *(float2*)(zout + off) = zf;
                    *(float2*)(dout + off) = zf;
                }
            }
        }
    }

    // ---- fused BN partial stats: per-CTA 64-row column sums (per wm half) ----
    if (BNS) {
        const int slot = blockIdx.y * 2 + wm;   // 0..63
#pragma unroll
        for (int ni = 0; ni < 4; ni++) {
            float a = s1x[ni], b = s1y[ni], p = s2x[ni], q = s2y[ni];
#pragma unroll
            for (int m = 4; m <= 16; m <<= 1) {
                a += __shfl_xor_sync(0xffffffffu, a, m);
                b += __shfl_xor_sync(0xffffffffu, b, m);
                p += __shfl_xor_sync(0xffffffffu, p, m);
                q += __shfl_xor_sync(0xffffffffu, q, m);
            }
            if (lane < 4) {   // grp==0 lanes hold 64-row totals
                const int cn = bn + wn * 32 + ni * 8 + (qk << 1);
                *(float2*)&g_psum [slot * HDIM + cn] = make_float2(a, b);
                *(float2*)&g_psum2[slot * HDIM + cn] = make_float2(p, q);
            }
        }
    }
}

// ---------------------------------------------------------------------------
// BN final reduce: grid = HDIM/64 blocks, block = 256 (64 cols x 4 row-threads)
// ---------------------------------------------------------------------------
__global__ void bnstat_final(const float* __restrict__ g, const float* __restrict__ be)
{
    __shared__ float sm1[256], sm2[256];
    const int tid = threadIdx.x;
    const int cl  = tid & 63;
    const int r0  = tid >> 6;    // 0..3
    const int c   = blockIdx.x * 64 + cl;
    float s = 0.f, s2 = 0.f;
#pragma unroll
    for (int r = r0; r < 64; r += 4) {
        s  += g_psum [r * HDIM + c];
        s2 += g_psum2[r * HDIM + c];
    }
    sm1[tid] = s; sm2[tid] = s2;
    __syncthreads();
    if (tid < 64) {
        s  = sm1[tid] + sm1[tid + 64] + sm1[tid + 128] + sm1[tid + 192];
        s2 = sm2[tid] + sm2[tid + 64] + sm2[tid + 128] + sm2[tid + 192];
        const float mu  = s * (1.f / (float)BATCH);
        const float var = fmaf(-mu, mu, s2 * (1.f / (float)BATCH));
        const int cc = blockIdx.x * 64 + tid;
        const float sc = g[cc] / sqrtf(var + 1e-5f);
        g_scale[cc] = sc;
        g_shift[cc] = fmaf(-mu, sc, be[cc]);
    }
}

// f32 -> f16 conversion (vectorized, grid-strided); n % 8 == 0
__global__ void f2h_k(const float* __restrict__ s, __half* __restrict__ d, int n)
{
    for (int i = (blockIdx.x * blockDim.x + threadIdx.x) * 8; i < n;
         i += gridDim.x * blockDim.x * 8) {
        float4 v0 = *(const float4*)(s + i);
        float4 v1 = *(const float4*)(s + i + 4);
        __half2 h0 = __floats2half2_rn(v0.x, v0.y);
        __half2 h1 = __floats2half2_rn(v0.z, v0.w);
        __half2 h2 = __floats2half2_rn(v1.x, v1.y);
        __half2 h3 = __floats2half2_rn(v1.z, v1.w);
        uint4 u;
        u.x = *(uint32_t*)&h0; u.y = *(uint32_t*)&h1;
        u.z = *(uint32_t*)&h2; u.w = *(uint32_t*)&h3;
        *(uint4*)(d + i) = u;
    }
}

// yt = z_next @ C^T + (ut*dt) @ D^T  -> out[4096*512 + r*25 + n]  (fp32 exact)
__global__ void yt_k(const float* __restrict__ ut, const float* __restrict__ Cm,
                     const float* __restrict__ Dm, const float* __restrict__ dtp,
                     float* __restrict__ out)
{
    const int i = blockIdx.x * blockDim.x + threadIdx.x;
    if (i >= BATCH * 25) return;
    const int r = i / 25;
    const int n = i - r * 25;

    const float4* zr = (const float4*)(g_zbuf + (size_t)r * DDIM);
    const float4* cr = (const float4*)(Cm + (size_t)n * DDIM);
    float acc = 0.f;
#pragma unroll 8
    for (int k = 0; k < DDIM / 4; k++) {
        float4 a = zr[k], b = cr[k];
        acc += a.x * b.x + a.y * b.y + a.z * b.z + a.w * b.w;
    }
    const float4* ur = (const float4*)(ut + (size_t)r * 64);
    const float4* dr = (const float4*)(Dm + (size_t)n * 64);
    float acc2 = 0.f;
#pragma unroll
    for (int k = 0; k < 16; k++) {
        float4 a = ur[k], b = dr[k];
        acc2 += a.x * b.x + a.y * b.y + a.z * b.z + a.w * b.w;
    }
    out[(size_t)BATCH * DDIM + i] = acc + (*dtp) * acc2;
}

// ===========================================================================
extern "C" void kernel_launch(void* const* d_in, const int* in_sizes, int n_in,
                              void* d_out, int out_size)
{
    (void)in_sizes; (void)n_in; (void)out_size;

    const float* z_dyn = (const float*)d_in[0];
    /* d_in[1] = z_static : unused by reference */
    const float* dtp   = (const float*)d_in[2];
    const float* ut    = (const float*)d_in[3];
    const float* eps   = (const float*)d_in[4];
    const float* W1  = (const float*)d_in[5];
    const float* b1  = (const float*)d_in[6];
    const float* g1  = (const float*)d_in[7];
    const float* be1 = (const float*)d_in[8];
    const float* W2  = (const float*)d_in[9];
    const float* b2  = (const float*)d_in[10];
    const float* g2  = (const float*)d_in[11];
    const float* be2 = (const float*)d_in[12];
    const float* W3  = (const float*)d_in[13];
    const float* b3  = (const float*)d_in[14];
    const float* Wd1 = (const float*)d_in[15];
    const float* bd1 = (const float*)d_in[16];
    const float* Wd2 = (const float*)d_in[17];
    const float* bd2 = (const float*)d_in[18];
    const float* Bsde= (const float*)d_in[19];
    const float* Cm  = (const float*)d_in[20];
    const float* Dm  = (const float*)d_in[21];
    float* out = (float*)d_out;

    float *zbuf, *F, *scl, *shf;
    __half *zh, *A1h, *A2h, *Th, *W1h, *W2h, *W3h, *Wd1h, *Wd2h, *Bsh, *uth;
    cudaGetSymbolAddress((void**)&zbuf, g_zbuf);
    cudaGetSymbolAddress((void**)&F,    g_F);
    cudaGetSymbolAddress((void**)&scl,  g_scale);
    cudaGetSymbolAddress((void**)&shf,  g_shift);
    cudaGetSymbolAddress((void**)&zh,   g_zh);
    cudaGetSymbolAddress((void**)&A1h,  g_A1h);
    cudaGetSymbolAddress((void**)&A2h,  g_A2h);
    cudaGetSymbolAddress((void**)&Th,   g_Th);
    cudaGetSymbolAddress((void**)&W1h,  g_W1h);
    cudaGetSymbolAddress((void**)&W2h,  g_W2h);
    cudaGetSymbolAddress((void**)&W3h,  g_W3h);
    cudaGetSymbolAddress((void**)&Wd1h, g_Wd1h);
    cudaGetSymbolAddress((void**)&Wd2h, g_Wd2h);
    cudaGetSymbolAddress((void**)&Bsh,  g_Bsh);
    cudaGetSymbolAddress((void**)&uth,  g_uth);

    const dim3 blk(256);
    const dim3 gridH(HDIM / BN, BATCH / BM);  // (8, 32)
    const dim3 gridD(DDIM / BN, BATCH / BM);  // (4, 32)

    // one-time (per launch) fp16 conversions
    f2h_k<<<128, 256>>>(W1,   W1h,  HDIM * DDIM);
    f2h_k<<<256, 256>>>(W2,   W2h,  HDIM * HDIM);
    f2h_k<<<128, 256>>>(W3,   W3h,  DDIM * HDIM);
    f2h_k<<<64,  256>>>(Wd1,  Wd1h, DDIM * DDIM);
    f2h_k<<<64,  256>>>(Wd2,  Wd2h, DDIM * DDIM);
    f2h_k<<<16,  256>>>(Bsde, Bsh,  DDIM * 64);
    f2h_k<<<64,  256>>>(ut,   uth,  BATCH * 64);
    f2h_k<<<256, 256>>>(z_dyn, zh,  BATCH * DDIM);

    for (int s = 0; s < NSTEPS; s++) {
        const float* eps_s = eps + (size_t)s * BATCH * DDIM;
        const float* zsrc  = (s == 0) ? z_dyn : zbuf;

        // drift layer 1 (+ fused BN1 partial stats), output fp16 A1h
        gemm_h<0, 0, 1, 1><<<gridH, blk>>>(zh, W1h, b1, nullptr, A1h,
                                           BATCH, HDIM, DDIM,
                                           nullptr, nullptr, nullptr, nullptr, nullptr,
                                           nullptr, nullptr, nullptr, nullptr);
        bnstat_final<<<HDIM / 64, 256>>>(g1, be1);
        // drift layer 2 (BN1+ReLU in staging; + fused BN2 stats), output fp16 A2h
        gemm_h<1, 0, 1, 1><<<gridH, blk>>>(A1h, W2h, b2, nullptr, A2h,
                                           BATCH, HDIM, HDIM,
                                           scl, shf, nullptr, nullptr, nullptr,
                                           nullptr, nullptr, nullptr, nullptr);
        bnstat_final<<<HDIM / 64, 256>>>(g2, be2);
        // drift layer 3 (BN2+ReLU in staging), output fp32 F
        gemm_h<1, 0, 0, 0><<<gridD, blk>>>(A2h, W3h, b3, F, nullptr,
                                           BATCH, DDIM, HDIM,
                                           scl, shf, nullptr, nullptr, nullptr,
                                           nullptr, nullptr, nullptr, nullptr);
        // diffusion layer 1 (tanh), output fp16 Th
        gemm_h<0, 1, 0, 1><<<gridD, blk>>>(zh, Wd1h, bd1, nullptr, Th,
                                           BATCH, DDIM, DDIM,
                                           nullptr, nullptr, nullptr, nullptr, nullptr,
                                           nullptr, nullptr, nullptr, nullptr);
        // diffusion layer 2 + Euler-Maruyama update (zin fp32 -> zout fp32 + zh fp16)
        gemm_h<0, 2, 0, 0><<<gridD, blk>>>(Th, Wd2h, bd2, nullptr, nullptr,
                                           BATCH, DDIM, DDIM,
                                           nullptr, nullptr, dtp, F, eps_s,
                                           zsrc, zbuf, zh, nullptr);
    }

    // z_next = z + dt*(ut @ B_sde^T) -> zbuf and out[0 : 4096*512)
    gemm_h<0, 3, 0, 0><<<gridD, blk>>>(uth, Bsh, nullptr, nullptr, nullptr,
                                       BATCH, DDIM, 64,
                                       nullptr, nullptr, dtp, nullptr, nullptr,
                                       zbuf, zbuf, nullptr, out);
    // yt -> out[4096*512 : +4096*25)
    yt_k<<<(BATCH * 25 + 255) / 256, 256>>>(ut, Cm, Dm, dtp, out);
}

// round 9
// speedup vs baseline: 6.9764x; 1.0975x over previous
#include <cuda_runtime.h>
#include <cuda_fp16.h>
#include <cstdint>
#include <math.h>

// ============================================================================
// ConditionedLatentSDETransition — fp16 HMMA, fused dual-region GEMMs, R8
//   * MODE0: [z@W1^T | z@Wd1^T] one launch (N=1536): A1h raw + BN stats | tanh->Th
//   * bn_apply: BN final reduce + in-place BN+ReLU transform of A1h/A2h
//   * MODE1: A1h@W2^T -> A2h + BN stats
//   * MODE2: [A2h@W3^T -> F | Th@Wd2^T -> softplus -> G] one launch (dual-K)
//   * z_update: z += h*F + sqrt_h*G*eps  (elementwise, writes fp32 + fp16 shadow)
//   * MODE3: z_next = z + dt*(ut@B^T) -> out ;  yt_k
//   * all GEMMs: pure cp.async 3-stage pipeline, ldmatrix + mma.m16n8k16
// ============================================================================

#define BM 128
#define BK 32
#define KS_LD 40     // 80B row stride: 16B-aligned, ldmatrix conflict-free (5r mod 8)
#define NSTG 3
#define SMEM_SZ (2 * NSTG * BM * KS_LD * 2)   // 61440 bytes

#define BATCH 4096
#define DDIM  512
#define HDIM  1024
#define NSTEPS 8

// ---- scratch (device globals; no allocation allowed) ----
__device__ float  g_zbuf[BATCH * DDIM];
__device__ float  g_F[BATCH * DDIM];
__device__ float  g_G[BATCH * DDIM];
__device__ float  g_psum [64 * HDIM];
__device__ float  g_psum2[64 * HDIM];

__device__ __half g_zh [BATCH * DDIM];
__device__ __half g_A1h[BATCH * HDIM];
__device__ __half g_A2h[BATCH * HDIM];
__device__ __half g_Th [BATCH * DDIM];
__device__ __half g_W1h [HDIM * DDIM];
__device__ __half g_W2h [HDIM * HDIM];
__device__ __half g_W3h [DDIM * HDIM];
__device__ __half g_Wd1h[DDIM * DDIM];
__device__ __half g_Wd2h[DDIM * DDIM];
__device__ __half g_Bsh [DDIM * 64];
__device__ __half g_uth [BATCH * 64];

__device__ __forceinline__ float softplus_f(float x) {
    return fmaxf(x, 0.f) + log1pf(expf(-fabsf(x)));   // jax.nn.softplus
}
__device__ __forceinline__ void cp16(void* sdst, const void* gsrc) {
    uint32_t sa = (uint32_t)__cvta_generic_to_shared(sdst);
    asm volatile("cp.async.cg.shared.global [%0], [%1], 16;" :: "r"(sa), "l"(gsrc));
}
__device__ __forceinline__ void cp_commit() { asm volatile("cp.async.commit_group;"); }
__device__ __forceinline__ void ldsm4(uint32_t* r, const void* p) {
    uint32_t a = (uint32_t)__cvta_generic_to_shared(p);
    asm volatile("ldmatrix.sync.aligned.m8n8.x4.shared.b16 {%0,%1,%2,%3}, [%4];"
                 : "=r"(r[0]), "=r"(r[1]), "=r"(r[2]), "=r"(r[3]) : "r"(a));
}
__device__ __forceinline__ void mma_f16(float* c, const uint32_t* a, const uint32_t* b) {
    asm volatile(
        "mma.sync.aligned.m16n8k16.row.col.f32.f16.f16.f32 "
        "{%0,%1,%2,%3}, {%4,%5,%6,%7}, {%8,%9}, {%0,%1,%2,%3};\n"
        : "+f"(c[0]), "+f"(c[1]), "+f"(c[2]), "+f"(c[3])
        : "r"(a[0]), "r"(a[1]), "r"(a[2]), "r"(a[3]), "r"(b[0]), "r"(b[1]));
}

// ---------------------------------------------------------------------------
// MODE 0: grid (12,32). bx<8:  zh @ W1^T -> A1h (N=1024) + BN stats, bias_a
//                       bx>=8: zh @ Wd1^T -> tanh -> Th (N=512),     bias_b
// MODE 1: grid (8,32).  A1h @ W2^T -> A2h (N=1024) + BN stats, bias_a. K=1024
// MODE 2: grid (8,32).  bx<4:  A2h @ W3^T -> F fp32 (K=1024), bias_a
//                       bx>=4: Th @ Wd2^T -> softplus+1e-5 -> G fp32 (K=512), bias_b
// MODE 3: grid (4,32).  uth @ Bsh^T (K=64); z = zbuf + dt*acc -> zbuf & dout
// ---------------------------------------------------------------------------
template<int MODE>
__global__ __launch_bounds__(256, 2)
void gemm16(const float* __restrict__ bias_a, const float* __restrict__ bias_b,
            const float* __restrict__ dtp, float* __restrict__ dout)
{
    extern __shared__ __half sh[];
    __half* Asm = sh;
    __half* Bsm = sh + NSTG * BM * KS_LD;

    const int tid = threadIdx.x, lane = tid & 31, wid = tid >> 5;
    const int wm = wid >> 2, wn = wid & 3, grp = lane >> 2, qk = lane & 3;
    const int bx = blockIdx.x, by = blockIdx.y;
    const int bm = by * BM;
    const int row0 = tid >> 2, seg8 = (tid & 3) << 3;

    bool regA = true;
    int K;
    const __half *Aop, *Wslab;
    if (MODE == 0) {
        regA = bx < 8; K = 512; Aop = g_zh;
        Wslab = regA ? g_W1h + (size_t)bx * 128 * 512
                     : g_Wd1h + (size_t)(bx - 8) * 128 * 512;
    } else if (MODE == 1) {
        K = 1024; Aop = g_A1h;
        Wslab = g_W2h + (size_t)bx * 128 * 1024;
    } else if (MODE == 2) {
        regA = bx < 4; K = regA ? 1024 : 512;
        Aop  = regA ? g_A2h : g_Th;
        Wslab = regA ? g_W3h + (size_t)bx * 128 * 1024
                     : g_Wd2h + (size_t)(bx - 4) * 128 * 512;
    } else {
        K = 64; Aop = g_uth;
        Wslab = g_Bsh + (size_t)bx * 128 * 64;
    }

    const __half* Ap0 = Aop + (size_t)(bm + row0) * K + seg8;
    const __half* Ap1 = Ap0 + (size_t)64 * K;
    const __half* Wp0 = Wslab + (size_t)row0 * K + seg8;
    const __half* Wp1 = Wp0 + (size_t)64 * K;

    float c[4][4][4];
#pragma unroll
    for (int mi = 0; mi < 4; mi++)
#pragma unroll
        for (int ni = 0; ni < 4; ni++)
#pragma unroll
            for (int j = 0; j < 4; j++) c[mi][ni][j] = 0.f;

    // ldmatrix lane offsets
    const int a_r = lane & 15;
    const int a_k = (lane >> 4) << 3;
    const int b_r = (lane & 7) + ((lane >> 4) << 3);
    const int b_k = ((lane >> 3) & 1) << 3;

    auto stage = [&](int t, int slot) {
        const size_t o = (size_t)t * BK;
        cp16(Asm + (slot * BM + row0)      * KS_LD + seg8, Ap0 + o);
        cp16(Asm + (slot * BM + row0 + 64) * KS_LD + seg8, Ap1 + o);
        cp16(Bsm + (slot * BM + row0)      * KS_LD + seg8, Wp0 + o);
        cp16(Bsm + (slot * BM + row0 + 64) * KS_LD + seg8, Wp1 + o);
        cp_commit();
    };

    const int T = K / BK;     // >= 2 in all modes
    stage(0, 0);
    stage(1, 1);

    for (int t = 0; t < T; t++) {
        asm volatile("cp.async.wait_group 1;");
        __syncthreads();
        if (t + 2 < T) stage(t + 2, (t + 2) % NSTG);
        else           cp_commit();   // empty group keeps wait-count arithmetic valid
        const int sb = t % NSTG;

#pragma unroll
        for (int ks = 0; ks < 2; ks++) {
            const int kk = ks * 16;
            uint32_t af[4][4], bf[4][2];
#pragma unroll
            for (int mi = 0; mi < 4; mi++)
                ldsm4(af[mi], Asm + (sb * BM + wm * 64 + mi * 16 + a_r) * KS_LD + kk + a_k);
#pragma unroll
            for (int nip = 0; nip < 2; nip++) {
                uint32_t tt[4];
                ldsm4(tt, Bsm + (sb * BM + wn * 32 + nip * 16 + b_r) * KS_LD + kk + b_k);
                bf[2 * nip][0] = tt[0]; bf[2 * nip][1] = tt[1];
                bf[2 * nip + 1][0] = tt[2]; bf[2 * nip + 1][1] = tt[3];
            }
#pragma unroll
            for (int mi = 0; mi < 4; mi++)
#pragma unroll
                for (int ni = 0; ni < 4; ni++)
                    mma_f16(c[mi][ni], af[mi], bf[ni]);
        }
    }

    // ---- epilogue ----
    float dtv = 0.f;
    if (MODE == 3) dtv = *dtp;

    float s1x[4], s1y[4], s2x[4], s2y[4];
    const bool do_stats = (MODE == 1) || (MODE == 0 && regA);
    if (do_stats) {
#pragma unroll
        for (int ni = 0; ni < 4; ni++) { s1x[ni]=0.f; s1y[ni]=0.f; s2x[ni]=0.f; s2y[ni]=0.f; }
    }

#pragma unroll
    for (int mi = 0; mi < 4; mi++) {
#pragma unroll
        for (int ni = 0; ni < 4; ni++) {
            const int r0 = bm + wm * 64 + mi * 16 + grp;
            const int lc = wn * 32 + ni * 8 + (qk << 1);
#pragma unroll
            for (int h = 0; h < 2; h++) {
                const int r = r0 + h * 8;
                const float ax = c[mi][ni][2 * h];
                const float ay = c[mi][ni][2 * h + 1];
                if (MODE == 0) {
                    if (regA) {
                        const int cn = bx * 128 + lc;
                        const size_t off = (size_t)r * HDIM + cn;
                        float2 b2 = *(const float2*)(bias_a + cn);
                        float vx = ax + b2.x, vy = ay + b2.y;
                        *(__half2*)(g_A1h + off) = __floats2half2_rn(vx, vy);
                        s1x[ni] += vx; s2x[ni] = fmaf(vx, vx, s2x[ni]);
                        s1y[ni] += vy; s2y[ni] = fmaf(vy, vy, s2y[ni]);
                    } else {
                        const int cn = (bx - 8) * 128 + lc;
                        const size_t off = (size_t)r * DDIM + cn;
                        float2 b2 = *(const float2*)(bias_b + cn);
                        *(__half2*)(g_Th + off) =
                            __floats2half2_rn(tanhf(ax + b2.x), tanhf(ay + b2.y));
                    }
                } else if (MODE == 1) {
                    const int cn = bx * 128 + lc;
                    const size_t off = (size_t)r * HDIM + cn;
                    float2 b2 = *(const float2*)(bias_a + cn);
                    float vx = ax + b2.x, vy = ay + b2.y;
                    *(__half2*)(g_A2h + off) = __floats2half2_rn(vx, vy);
                    s1x[ni] += vx; s2x[ni] = fmaf(vx, vx, s2x[ni]);
                    s1y[ni] += vy; s2y[ni] = fmaf(vy, vy, s2y[ni]);
                } else if (MODE == 2) {
                    if (regA) {
                        const int cn = bx * 128 + lc;
                        const size_t off = (size_t)r * DDIM + cn;
                        float2 b2 = *(const float2*)(bias_a + cn);
                        *(float2*)(g_F + off) = make_float2(ax + b2.x, ay + b2.y);
                    } else {
                        const int cn = (bx - 4) * 128 + lc;
                        const size_t off = (size_t)r * DDIM + cn;
                        float2 b2 = *(const float2*)(bias_b + cn);
                        *(float2*)(g_G + off) =
                            make_float2(softplus_f(ax + b2.x) + 1e-5f,
                                        softplus_f(ay + b2.y) + 1e-5f);
                    }
                } else { // MODE 3
                    const int cn = bx * 128 + lc;
                    const size_t off = (size_t)r * DDIM + cn;
                    float2 zf = *(const float2*)(g_zbuf + off);
                    zf.x = fmaf(dtv, ax, zf.x);
                    zf.y = fmaf(dtv, ay, zf.y);
                    *(float2*)(g_zbuf + off) = zf;
                    *(float2*)(dout + off)   = zf;
                }
            }
        }
    }

    if (do_stats) {
        const int slot = by * 2 + wm;   // 0..63
#pragma unroll
        for (int ni = 0; ni < 4; ni++) {
            float a = s1x[ni], b = s1y[ni], p = s2x[ni], q = s2y[ni];
#pragma unroll
            for (int m = 4; m <= 16; m <<= 1) {
                a += __shfl_xor_sync(0xffffffffu, a, m);
                b += __shfl_xor_sync(0xffffffffu, b, m);
                p += __shfl_xor_sync(0xffffffffu, p, m);
                q += __shfl_xor_sync(0xffffffffu, q, m);
            }
            if (lane < 4) {
                const int cn = bx * 128 + wn * 32 + ni * 8 + (qk << 1);
                *(float2*)&g_psum [slot * HDIM + cn] = make_float2(a, b);
                *(float2*)&g_psum2[slot * HDIM + cn] = make_float2(p, q);
            }
        }
    }
}

// ---------------------------------------------------------------------------
// BN finish: reduce 64 partial slots -> scale/shift for 64 cols, then apply
// BN+ReLU in place to X (fp16, row stride HDIM). grid (16, 8), 256 threads.
// ---------------------------------------------------------------------------
__global__ void bn_apply(__half* __restrict__ X,
                         const float* __restrict__ g, const float* __restrict__ be)
{
    __shared__ float tmp1[256], tmp2[256], ssc[64], ssh[64];
    const int tid = threadIdx.x;
    const int c  = tid & 63;
    const int r0 = tid >> 6;          // 0..3
    const int c0 = blockIdx.x * 64;

    float s = 0.f, s2 = 0.f;
#pragma unroll
    for (int r = r0; r < 64; r += 4) {
        s  += g_psum [r * HDIM + c0 + c];
        s2 += g_psum2[r * HDIM + c0 + c];
    }
    tmp1[tid] = s; tmp2[tid] = s2;
    __syncthreads();
    if (tid < 64) {
        s  = tmp1[tid] + tmp1[tid + 64] + tmp1[tid + 128] + tmp1[tid + 192];
        s2 = tmp2[tid] + tmp2[tid + 64] + tmp2[tid + 128] + tmp2[tid + 192];
        const float mu  = s * (1.f / (float)BATCH);
        const float var = fmaf(-mu, mu, s2 * (1.f / (float)BATCH));
        const float sc  = g[c0 + tid] / sqrtf(var + 1e-5f);
        ssc[tid] = sc;
        ssh[tid] = fmaf(-mu, sc, be[c0 + tid]);
    }
    __syncthreads();

    const int warp = tid >> 5, lane = tid & 31;
    const float scx = ssc[lane * 2],     shx = ssh[lane * 2];
    const float scy = ssc[lane * 2 + 1], shy = ssh[lane * 2 + 1];
    const int rbase = blockIdx.y * 512 + warp * 64;
#pragma unroll 4
    for (int i = 0; i < 64; i++) {
        __half2* p = (__half2*)(X + (size_t)(rbase + i) * HDIM + c0) + lane;
        float2 f = __half22float2(*p);
        f.x = fmaxf(fmaf(f.x, scx, shx), 0.f);
        f.y = fmaxf(fmaf(f.y, scy, shy), 0.f);
        *p = __float22half2_rn(f);
    }
}

// ---------------------------------------------------------------------------
// Euler-Maruyama update: z = zin + h*F + sqrt_h*G*eps  (fp32 + fp16 shadow)
// ---------------------------------------------------------------------------
__global__ void z_update(const float* __restrict__ dtp,
                         const float* __restrict__ eps,
                         const float* __restrict__ zin)
{
    const int i4 = blockIdx.x * blockDim.x + threadIdx.x;
    if (i4 >= BATCH * DDIM / 4) return;
    const float dt = *dtp;
    const float h  = dt * (1.f / (float)NSTEPS);
    const float sq = sqrtf(fabsf(h) + 1e-8f);

    float4 z = ((const float4*)zin)[i4];
    float4 f = ((const float4*)g_F)[i4];
    float4 g = ((const float4*)g_G)[i4];
    float4 e = ((const float4*)eps)[i4];
    z.x = z.x + h * f.x + sq * g.x * e.x;
    z.y = z.y + h * f.y + sq * g.y * e.y;
    z.z = z.z + h * f.z + sq * g.z * e.z;
    z.w = z.w + h * f.w + sq * g.w * e.w;
    ((float4*)g_zbuf)[i4] = z;
    __half2 h0 = __floats2half2_rn(z.x, z.y);
    __half2 h1 = __floats2half2_rn(z.z, z.w);
    uint2 u; u.x = *(uint32_t*)&h0; u.y = *(uint32_t*)&h1;
    *(uint2*)(g_zh + (size_t)i4 * 4) = u;
}

// ---------------------------------------------------------------------------
// one-shot fp32 -> fp16 conversion of all operands; grid (X, 8)
// ---------------------------------------------------------------------------
__global__ void cvt_all(const float* s0, const float* s1, const float* s2,
                        const float* s3, const float* s4, const float* s5,
                        const float* s6, const float* s7)
{
    const float* srcs[8] = {s0, s1, s2, s3, s4, s5, s6, s7};
    __half* dsts[8] = {g_W1h, g_W2h, g_W3h, g_Wd1h, g_Wd2h, g_Bsh, g_uth, g_zh};
    const int ns[8] = {HDIM*DDIM, HDIM*HDIM, DDIM*HDIM, DDIM*DDIM,
                       DDIM*DDIM, DDIM*64, BATCH*64, BATCH*DDIM};
    const int seg = blockIdx.y;
    const float* s = srcs[seg];
    __half* d = dsts[seg];
    const int n = ns[seg];
    for (int i = (blockIdx.x * blockDim.x + threadIdx.x) * 8; i < n;
         i += gridDim.x * blockDim.x * 8) {
        float4 v0 = *(const float4*)(s + i);
        float4 v1 = *(const float4*)(s + i + 4);
        __half2 h0 = __floats2half2_rn(v0.x, v0.y);
        __half2 h1 = __floats2half2_rn(v0.z, v0.w);
        __half2 h2 = __floats2half2_rn(v1.x, v1.y);
        __half2 h3 = __floats2half2_rn(v1.z, v1.w);
        uint4 u;
        u.x = *(uint32_t*)&h0; u.y = *(uint32_t*)&h1;
        u.z = *(uint32_t*)&h2; u.w = *(uint32_t*)&h3;
        *(uint4*)(d + i) = u;
    }
}

// yt = z_next @ C^T + (ut*dt) @ D^T  -> out[4096*512 + r*25 + n]  (fp32 exact)
__global__ void yt_k(const float* __restrict__ ut, const float* __restrict__ Cm,
                     const float* __restrict__ Dm, const float* __restrict__ dtp,
                     float* __restrict__ out)
{
    const int i = blockIdx.x * blockDim.x + threadIdx.x;
    if (i >= BATCH * 25) return;
    const int r = i / 25;
    const int n = i - r * 25;

    const float4* zr = (const float4*)(g_zbuf + (size_t)r * DDIM);
    const float4* cr = (const float4*)(Cm + (size_t)n * DDIM);
    float acc = 0.f;
#pragma unroll 8
    for (int k = 0; k < DDIM / 4; k++) {
        float4 a = zr[k], b = cr[k];
        acc += a.x * b.x + a.y * b.y + a.z * b.z + a.w * b.w;
    }
    const float4* ur = (const float4*)(ut + (size_t)r * 64);
    const float4* dr = (const float4*)(Dm + (size_t)n * 64);
    float acc2 = 0.f;
#pragma unroll
    for (int k = 0; k < 16; k++) {
        float4 a = ur[k], b = dr[k];
        acc2 += a.x * b.x + a.y * b.y + a.z * b.z + a.w * b.w;
    }
    out[(size_t)BATCH * DDIM + i] = acc + (*dtp) * acc2;
}

// ===========================================================================
extern "C" void kernel_launch(void* const* d_in, const int* in_sizes, int n_in,
                              void* d_out, int out_size)
{
    (void)in_sizes; (void)n_in; (void)out_size;

    const float* z_dyn = (const float*)d_in[0];
    /* d_in[1] = z_static : unused by reference */
    const float* dtp   = (const float*)d_in[2];
    const float* ut    = (const float*)d_in[3];
    const float* eps   = (const float*)d_in[4];
    const float* W1  = (const float*)d_in[5];
    const float* b1  = (const float*)d_in[6];
    const float* g1  = (const float*)d_in[7];
    const float* be1 = (const float*)d_in[8];
    const float* W2  = (const float*)d_in[9];
    const float* b2  = (const float*)d_in[10];
    const float* g2  = (const float*)d_in[11];
    const float* be2 = (const float*)d_in[12];
    const float* W3  = (const float*)d_in[13];
    const float* b3  = (const float*)d_in[14];
    const float* Wd1 = (const float*)d_in[15];
    const float* bd1 = (const float*)d_in[16];
    const float* Wd2 = (const float*)d_in[17];
    const float* bd2 = (const float*)d_in[18];
    const float* Bsde= (const float*)d_in[19];
    const float* Cm  = (const float*)d_in[20];
    const float* Dm  = (const float*)d_in[21];
    float* out = (float*)d_out;

    __half *A1h, *A2h;
    float* zbuf;
    cudaGetSymbolAddress((void**)&A1h,  g_A1h);
    cudaGetSymbolAddress((void**)&A2h,  g_A2h);
    cudaGetSymbolAddress((void**)&zbuf, g_zbuf);

    cudaFuncSetAttribute(gemm16<0>, cudaFuncAttributeMaxDynamicSharedMemorySize, SMEM_SZ);
    cudaFuncSetAttribute(gemm16<1>, cudaFuncAttributeMaxDynamicSharedMemorySize, SMEM_SZ);
    cudaFuncSetAttribute(gemm16<2>, cudaFuncAttributeMaxDynamicSharedMemorySize, SMEM_SZ);
    cudaFuncSetAttribute(gemm16<3>, cudaFuncAttributeMaxDynamicSharedMemorySize, SMEM_SZ);

    const dim3 blk(256);

    // one-shot conversions (weights, ut, z)
    cvt_all<<<dim3(256, 8), 256>>>(W1, W2, W3, Wd1, Wd2, Bsde, ut, z_dyn);

    for (int s = 0; s < NSTEPS; s++) {
        const float* eps_s = eps + (size_t)s * BATCH * DDIM;
        const float* zsrc  = (s == 0) ? z_dyn : zbuf;

        // [drift L1 | diffusion L1] fused; A1h raw + BN1 stats; Th = tanh
        gemm16<0><<<dim3(12, 32), blk, SMEM_SZ>>>(b1, bd1, nullptr, nullptr);
        // BN1 finish + in-place relu(bn(A1h))
        bn_apply<<<dim3(16, 8), 256>>>(A1h, g1, be1);
        // drift L2; A2h raw + BN2 stats
        gemm16<1><<<dim3(8, 32), blk, SMEM_SZ>>>(b2, nullptr, nullptr, nullptr);
        // BN2 finish + in-place relu(bn(A2h))
        bn_apply<<<dim3(16, 8), 256>>>(A2h, g2, be2);
        // [drift L3 -> F | diffusion L2 -> softplus -> G] fused dual-K
        gemm16<2><<<dim3(8, 32), blk, SMEM_SZ>>>(b3, bd2, nullptr, nullptr);
        // Euler-Maruyama update
        z_update<<<(BATCH * DDIM / 4 + 255) / 256, 256>>>(dtp, eps_s, zsrc);
    }

    // z_next = z + dt*(ut @ B_sde^T) -> zbuf and out[0 : 4096*512)
    gemm16<3><<<dim3(4, 32), blk, SMEM_SZ>>>(nullptr, nullptr, dtp, out);
    // yt -> out[4096*512 : +4096*25)
    yt_k<<<(BATCH * 25 + 255) / 256, 256>>>(ut, Cm, Dm, dtp, out);
}

// round 11
// speedup vs baseline: 7.1685x; 1.0275x over previous
#include <cuda_runtime.h>
#include <cuda_fp16.h>
#include <cstdint>
#include <math.h>

// ============================================================================
// ConditionedLatentSDETransition — fp16 HMMA R11
//   * MODE0: [z@W1^T -> A1h + BN1 stats | z@Wd1^T -> tanh -> Th]  (N=1536)
//   * bnstat_final: tiny reduce -> g_scale/g_shift
//   * MODE1: bn_relu(A1h) @ W2^T -> A2h + BN2 stats   [BN fused in A-staging]
//   * MODE2: [bn_relu(A2h)@W3^T -> Fh | Th@Wd2^T -> softplus -> Gh]  (fp16 out)
//   * z_update: z += h*F + sqrt_h*G*eps  (fp32 master + fp16 shadow)
//   * MODE3: z_next = z + dt*(ut@B^T) -> out ; yt_k
//   * GEMMs: 4-stage cp.async pipeline, ldmatrix + mma.m16n8k16
// ============================================================================

#define BM 128
#define BK 32
#define KS_LD 40     // 80B row stride: 16B-aligned, ldmatrix conflict-free
#define NSTG 4
#define SMEM_SZ (2 * NSTG * BM * KS_LD * 2)   // 81920 bytes

#define BATCH 4096
#define DDIM  512
#define HDIM  1024
#define NSTEPS 8

// ---- scratch (device globals; no allocation allowed) ----
__device__ float  g_zbuf[BATCH * DDIM];
__device__ float  g_psum [64 * HDIM];
__device__ float  g_psum2[64 * HDIM];
__device__ float  g_scale[HDIM];
__device__ float  g_shift[HDIM];

__device__ __half g_zh [BATCH * DDIM];
__device__ __half g_A1h[BATCH * HDIM];
__device__ __half g_A2h[BATCH * HDIM];
__device__ __half g_Th [BATCH * DDIM];
__device__ __half g_Fh [BATCH * DDIM];
__device__ __half g_Gh [BATCH * DDIM];
__device__ __half g_W1h [HDIM * DDIM];
__device__ __half g_W2h [HDIM * HDIM];
__device__ __half g_W3h [DDIM * HDIM];
__device__ __half g_Wd1h[DDIM * DDIM];
__device__ __half g_Wd2h[DDIM * DDIM];
__device__ __half g_Bsh [DDIM * 64];
__device__ __half g_uth [BATCH * 64];

__device__ __forceinline__ float softplus_f(float x) {
    return fmaxf(x, 0.f) + log1pf(expf(-fabsf(x)));   // jax.nn.softplus
}
__device__ __forceinline__ void cp16(void* sdst, const void* gsrc) {
    uint32_t sa = (uint32_t)__cvta_generic_to_shared(sdst);
    asm volatile("cp.async.cg.shared.global [%0], [%1], 16;" :: "r"(sa), "l"(gsrc));
}
__device__ __forceinline__ void cp_commit() { asm volatile("cp.async.commit_group;"); }
__device__ __forceinline__ void cp_wait2()  { asm volatile("cp.async.wait_group 2;"); }
__device__ __forceinline__ void ldsm4(uint32_t* r, const void* p) {
    uint32_t a = (uint32_t)__cvta_generic_to_shared(p);
    asm volatile("ldmatrix.sync.aligned.m8n8.x4.shared.b16 {%0,%1,%2,%3}, [%4];"
                 : "=r"(r[0]), "=r"(r[1]), "=r"(r[2]), "=r"(r[3]) : "r"(a));
}
__device__ __forceinline__ void mma_f16(float* c, const uint32_t* a, const uint32_t* b) {
    asm volatile(
        "mma.sync.aligned.m16n8k16.row.col.f32.f16.f16.f32 "
        "{%0,%1,%2,%3}, {%4,%5,%6,%7}, {%8,%9}, {%0,%1,%2,%3};\n"
        : "+f"(c[0]), "+f"(c[1]), "+f"(c[2]), "+f"(c[3])
        : "r"(a[0]), "r"(a[1]), "r"(a[2]), "r"(a[3]), "r"(b[0]), "r"(b[1]));
}

// ---------------------------------------------------------------------------
// MODE 0: grid (12,32). bx<8:  zh @ W1^T -> A1h + BN stats.  bx>=8: tanh -> Th
// MODE 1: grid (8,32).  bn_relu(A1h) @ W2^T -> A2h + BN stats. K=1024
// MODE 2: grid (8,32).  bx<4: bn_relu(A2h)@W3^T -> Fh (K=1024)
//                       bx>=4: Th@Wd2^T -> softplus -> Gh (K=512)
// MODE 3: grid (4,32).  uth @ Bsh^T (K=64); z = zbuf + dt*acc -> zbuf & dout
// ---------------------------------------------------------------------------
template<int MODE>
__global__ __launch_bounds__(256, 2)
void gemm16(const float* __restrict__ bias_a, const float* __restrict__ bias_b,
            const float* __restrict__ dtp, float* __restrict__ dout)
{
    extern __shared__ __half sh[];
    __half* Asm = sh;
    __half* Bsm = sh + NSTG * BM * KS_LD;

    const int tid = threadIdx.x, lane = tid & 31, wid = tid >> 5;
    const int wm = wid >> 2, wn = wid & 3, grp = lane >> 2, qk = lane & 3;
    const int bx = blockIdx.x, by = blockIdx.y;
    const int bm = by * BM;
    const int row0 = tid >> 2, seg8 = (tid & 3) << 3;

    bool regA = true;
    int K;
    const __half *Aop, *Wslab;
    if (MODE == 0) {
        regA = bx < 8; K = 512; Aop = g_zh;
        Wslab = regA ? g_W1h + (size_t)bx * 128 * 512
                     : g_Wd1h + (size_t)(bx - 8) * 128 * 512;
    } else if (MODE == 1) {
        K = 1024; Aop = g_A1h;
        Wslab = g_W2h + (size_t)bx * 128 * 1024;
    } else if (MODE == 2) {
        regA = bx < 4; K = regA ? 1024 : 512;
        Aop  = regA ? g_A2h : g_Th;
        Wslab = regA ? g_W3h + (size_t)bx * 128 * 1024
                     : g_Wd2h + (size_t)(bx - 4) * 128 * 512;
    } else {
        K = 64; Aop = g_uth;
        Wslab = g_Bsh + (size_t)bx * 128 * 64;
    }
    // does this CTA apply BN+ReLU to A during staging?
    const bool trA = (MODE == 1) || (MODE == 2 && regA);

    const __half* Ap0 = Aop + (size_t)(bm + row0) * K + seg8;
    const __half* Ap1 = Ap0 + (size_t)64 * K;
    const __half* Wp0 = Wslab + (size_t)row0 * K + seg8;
    const __half* Wp1 = Wp0 + (size_t)64 * K;

    float c[4][4][4];
#pragma unroll
    for (int mi = 0; mi < 4; mi++)
#pragma unroll
        for (int ni = 0; ni < 4; ni++)
#pragma unroll
            for (int j = 0; j < 4; j++) c[mi][ni][j] = 0.f;

    const int a_r = lane & 15;
    const int a_k = (lane >> 4) << 3;
    const int b_r = (lane & 7) + ((lane >> 4) << 3);
    const int b_k = ((lane >> 3) & 1) << 3;

    uint4 a0r, a1r;                      // register-held A rows (transform path)

    auto ldgA = [&](int t) {
        const size_t o = (size_t)t * BK;
        a0r = *(const uint4*)(Ap0 + o);
        a1r = *(const uint4*)(Ap1 + o);
    };
    auto cpA = [&](int t, int slot) {
        const size_t o = (size_t)t * BK;
        cp16(Asm + (slot * BM + row0)      * KS_LD + seg8, Ap0 + o);
        cp16(Asm + (slot * BM + row0 + 64) * KS_LD + seg8, Ap1 + o);
    };
    auto cpB = [&](int t, int slot) {
        const size_t o = (size_t)t * BK;
        cp16(Bsm + (slot * BM + row0)      * KS_LD + seg8, Wp0 + o);
        cp16(Bsm + (slot * BM + row0 + 64) * KS_LD + seg8, Wp1 + o);
    };
    // transform a0r/a1r with BN(scale,shift)+ReLU at absolute k = t*BK+seg8, store
    auto trsts = [&](int t, int slot) {
        const int kb = t * BK + seg8;
        float4 sc0 = *(const float4*)(g_scale + kb);
        float4 sc1 = *(const float4*)(g_scale + kb + 4);
        float4 sf0 = *(const float4*)(g_shift + kb);
        float4 sf1 = *(const float4*)(g_shift + kb + 4);
        const float scv[8] = {sc0.x, sc0.y, sc0.z, sc0.w, sc1.x, sc1.y, sc1.z, sc1.w};
        const float sfv[8] = {sf0.x, sf0.y, sf0.z, sf0.w, sf1.x, sf1.y, sf1.z, sf1.w};
        uint4 o0 = a0r, o1 = a1r;
        __half2* h0 = (__half2*)&o0;
        __half2* h1 = (__half2*)&o1;
#pragma unroll
        for (int j = 0; j < 4; j++) {
            float2 f0 = __half22float2(h0[j]);
            float2 f1 = __half22float2(h1[j]);
            f0.x = fmaxf(fmaf(f0.x, scv[2*j],   sfv[2*j]),   0.f);
            f0.y = fmaxf(fmaf(f0.y, scv[2*j+1], sfv[2*j+1]), 0.f);
            f1.x = fmaxf(fmaf(f1.x, scv[2*j],   sfv[2*j]),   0.f);
            f1.y = fmaxf(fmaf(f1.y, scv[2*j+1], sfv[2*j+1]), 0.f);
            h0[j] = __float22half2_rn(f0);
            h1[j] = __float22half2_rn(f1);
        }
        *(uint4*)&Asm[(slot * BM + row0)      * KS_LD + seg8] = o0;
        *(uint4*)&Asm[(slot * BM + row0 + 64) * KS_LD + seg8] = o1;
    };

    const int T = K / BK;    // tiles; >= 2 always

    // ---- prologue: stage tiles 0..2 (empty commits beyond T) ----
#pragma unroll
    for (int p = 0; p < 3; p++) {
        if (p < T) {
            if (trA) ldgA(p); else cpA(p, p);
            cpB(p, p);
            cp_commit();
            if (trA) trsts(p, p);
        } else {
            cp_commit();
        }
    }

    for (int t = 0; t < T; t++) {
        cp_wait2();
        __syncthreads();

        const int tf = t + 3;
        const int slot = tf & 3;
        const bool have = tf < T;
        if (have) {
            if (trA) ldgA(tf); else cpA(tf, slot);
            cpB(tf, slot);
        }
        cp_commit();

        const int sb = t & 3;
#pragma unroll
        for (int ks = 0; ks < 2; ks++) {
            const int kk = ks * 16;
            uint32_t af[4][4], bf[4][2];
#pragma unroll
            for (int mi = 0; mi < 4; mi++)
                ldsm4(af[mi], Asm + (sb * BM + wm * 64 + mi * 16 + a_r) * KS_LD + kk + a_k);
#pragma unroll
            for (int nip = 0; nip < 2; nip++) {
                uint32_t tt[4];
                ldsm4(tt, Bsm + (sb * BM + wn * 32 + nip * 16 + b_r) * KS_LD + kk + b_k);
                bf[2 * nip][0] = tt[0]; bf[2 * nip][1] = tt[1];
                bf[2 * nip + 1][0] = tt[2]; bf[2 * nip + 1][1] = tt[3];
            }
#pragma unroll
            for (int mi = 0; mi < 4; mi++)
#pragma unroll
                for (int ni = 0; ni < 4; ni++)
                    mma_f16(c[mi][ni], af[mi], bf[ni]);
        }

        if (have && trA) trsts(tf, slot);   // STS after MMA: hides LDG latency
    }

    // ---- epilogue ----
    float dtv = 0.f;
    if (MODE == 3) dtv = *dtp;

    float s1x[4], s1y[4], s2x[4], s2y[4];
    const bool do_stats = (MODE == 1) || (MODE == 0 && regA);
    if (do_stats) {
#pragma unroll
        for (int ni = 0; ni < 4; ni++) { s1x[ni]=0.f; s1y[ni]=0.f; s2x[ni]=0.f; s2y[ni]=0.f; }
    }

#pragma unroll
    for (int mi = 0; mi < 4; mi++) {
#pragma unroll
        for (int ni = 0; ni < 4; ni++) {
            const int r0 = bm + wm * 64 + mi * 16 + grp;
            const int lc = wn * 32 + ni * 8 + (qk << 1);
#pragma unroll
            for (int h = 0; h < 2; h++) {
                const int r = r0 + h * 8;
                const float ax = c[mi][ni][2 * h];
                const float ay = c[mi][ni][2 * h + 1];
                if (MODE == 0) {
                    if (regA) {
                        const int cn = bx * 128 + lc;
                        const size_t off = (size_t)r * HDIM + cn;
                        float2 b2 = *(const float2*)(bias_a + cn);
                        float vx = ax + b2.x, vy = ay + b2.y;
                        *(__half2*)(g_A1h + off) = __floats2half2_rn(vx, vy);
                        s1x[ni] += vx; s2x[ni] = fmaf(vx, vx, s2x[ni]);
                        s1y[ni] += vy; s2y[ni] = fmaf(vy, vy, s2y[ni]);
                    } else {
                        const int cn = (bx - 8) * 128 + lc;
                        const size_t off = (size_t)r * DDIM + cn;
                        float2 b2 = *(const float2*)(bias_b + cn);
                        *(__half2*)(g_Th + off) =
                            __floats2half2_rn(tanhf(ax + b2.x), tanhf(ay + b2.y));
                    }
                } else if (MODE == 1) {
                    const int cn = bx * 128 + lc;
                    const size_t off = (size_t)r * HDIM + cn;
                    float2 b2 = *(const float2*)(bias_a + cn);
                    float vx = ax + b2.x, vy = ay + b2.y;
                    *(__half2*)(g_A2h + off) = __floats2half2_rn(vx, vy);
                    s1x[ni] += vx; s2x[ni] = fmaf(vx, vx, s2x[ni]);
                    s1y[ni] += vy; s2y[ni] = fmaf(vy, vy, s2y[ni]);
                } else if (MODE == 2) {
                    if (regA) {
                        const int cn = bx * 128 + lc;
                        const size_t off = (size_t)r * DDIM + cn;
                        float2 b2 = *(const float2*)(bias_a + cn);
                        *(__half2*)(g_Fh + off) = __floats2half2_rn(ax + b2.x, ay + b2.y);
                    } else {
                        const int cn = (bx - 4) * 128 + lc;
                        const size_t off = (size_t)r * DDIM + cn;
                        float2 b2 = *(const float2*)(bias_b + cn);
                        *(__half2*)(g_Gh + off) =
                            __floats2half2_rn(softplus_f(ax + b2.x) + 1e-5f,
                                              softplus_f(ay + b2.y) + 1e-5f);
                    }
                } else { // MODE 3
                    const int cn = bx * 128 + lc;
                    const size_t off = (size_t)r * DDIM + cn;
                    float2 zf = *(const float2*)(g_zbuf + off);
                    zf.x = fmaf(dtv, ax, zf.x);
                    zf.y = fmaf(dtv, ay, zf.y);
                    *(float2*)(g_zbuf + off) = zf;
                    *(float2*)(dout + off)   = zf;
                }
            }
        }
    }

    if (do_stats) {
        const int slot = by * 2 + wm;   // 0..63
#pragma unroll
        for (int ni = 0; ni < 4; ni++) {
            float a = s1x[ni], b = s1y[ni], p = s2x[ni], q = s2y[ni];
#pragma unroll
            for (int m = 4; m <= 16; m <<= 1) {
                a += __shfl_xor_sync(0xffffffffu, a, m);
                b += __shfl_xor_sync(0xffffffffu, b, m);
                p += __shfl_xor_sync(0xffffffffu, p, m);
                q += __shfl_xor_sync(0xffffffffu, q, m);
            }
            if (lane < 4) {
                const int cn = bx * 128 + wn * 32 + ni * 8 + (qk << 1);
                *(float2*)&g_psum [slot * HDIM + cn] = make_float2(a, b);
                *(float2*)&g_psum2[slot * HDIM + cn] = make_float2(p, q);
            }
        }
    }
}

// ---------------------------------------------------------------------------
// BN final reduce -> g_scale/g_shift. grid = 16 blocks, 256 threads.
// ---------------------------------------------------------------------------
__global__ void bnstat_final(const float* __restrict__ g, const float* __restrict__ be)
{
    __shared__ float sm1[256], sm2[256];
    const int tid = threadIdx.x;
    const int cl  = tid & 63;
    const int r0  = tid >> 6;    // 0..3
    const int c   = blockIdx.x * 64 + cl;
    float s = 0.f, s2 = 0.f;
#pragma unroll
    for (int r = r0; r < 64; r += 4) {
        s  += g_psum [r * HDIM + c];
        s2 += g_psum2[r * HDIM + c];
    }
    sm1[tid] = s; sm2[tid] = s2;
    __syncthreads();
    if (tid < 64) {
        s  = sm1[tid] + sm1[tid + 64] + sm1[tid + 128] + sm1[tid + 192];
        s2 = sm2[tid] + sm2[tid + 64] + sm2[tid + 128] + sm2[tid + 192];
        const float mu  = s * (1.f / (float)BATCH);
        const float var = fmaf(-mu, mu, s2 * (1.f / (float)BATCH));
        const int cc = blockIdx.x * 64 + tid;
        const float sc = g[cc] / sqrtf(var + 1e-5f);
        g_scale[cc] = sc;
        g_shift[cc] = fmaf(-mu, sc, be[cc]);
    }
}

// ---------------------------------------------------------------------------
// Euler-Maruyama: z = zin + h*F + sqrt_h*G*eps  (F/G fp16; fp32 z + fp16 shadow)
// ---------------------------------------------------------------------------
__global__ void z_update(const float* __restrict__ dtp,
                         const float* __restrict__ eps,
                         const float* __restrict__ zin)
{
    const int i4 = blockIdx.x * blockDim.x + threadIdx.x;
    if (i4 >= BATCH * DDIM / 4) return;
    const float dt = *dtp;
    const float h  = dt * (1.f / (float)NSTEPS);
    const float sq = sqrtf(fabsf(h) + 1e-8f);

    float4 z = ((const float4*)zin)[i4];
    float4 e = ((const float4*)eps)[i4];
    uint2 fu = *(const uint2*)(g_Fh + (size_t)i4 * 4);
    uint2 gu = *(const uint2*)(g_Gh + (size_t)i4 * 4);
    float2 f01 = __half22float2(*(__half2*)&fu.x);
    float2 f23 = __half22float2(*(__half2*)&fu.y);
    float2 g01 = __half22float2(*(__half2*)&gu.x);
    float2 g23 = __half22float2(*(__half2*)&gu.y);
    z.x = z.x + h * f01.x + sq * g01.x * e.x;
    z.y = z.y + h * f01.y + sq * g01.y * e.y;
    z.z = z.z + h * f23.x + sq * g23.x * e.z;
    z.w = z.w + h * f23.y + sq * g23.y * e.w;
    ((float4*)g_zbuf)[i4] = z;
    __half2 h0 = __floats2half2_rn(z.x, z.y);
    __half2 h1 = __floats2half2_rn(z.z, z.w);
    uint2 u; u.x = *(uint32_t*)&h0; u.y = *(uint32_t*)&h1;
    *(uint2*)(g_zh + (size_t)i4 * 4) = u;
}

// ---------------------------------------------------------------------------
// one-shot fp32 -> fp16 conversion of all operands; grid (X, 8)
// ---------------------------------------------------------------------------
__global__ void cvt_all(const float* s0, const float* s1, const float* s2,
                        const float* s3, const float* s4, const float* s5,
                        const float* s6, const float* s7)
{
    const float* srcs[8] = {s0, s1, s2, s3, s4, s5, s6, s7};
    __half* dsts[8] = {g_W1h, g_W2h, g_W3h, g_Wd1h, g_Wd2h, g_Bsh, g_uth, g_zh};
    const int ns[8] = {HDIM*DDIM, HDIM*HDIM, DDIM*HDIM, DDIM*DDIM,
                       DDIM*DDIM, DDIM*64, BATCH*64, BATCH*DDIM};
    const int seg = blockIdx.y;
    const float* s = srcs[seg];
    __half* d = dsts[seg];
    const int n = ns[seg];
    for (int i = (blockIdx.x * blockDim.x + threadIdx.x) * 8; i < n;
         i += gridDim.x * blockDim.x * 8) {
        float4 v0 = *(const float4*)(s + i);
        float4 v1 = *(const float4*)(s + i + 4);
        __half2 h0 = __floats2half2_rn(v0.x, v0.y);
        __half2 h1 = __floats2half2_rn(v0.z, v0.w);
        __half2 h2 = __floats2half2_rn(v1.x, v1.y);
        __half2 h3 = __floats2half2_rn(v1.z, v1.w);
        uint4 u;
        u.x = *(uint32_t*)&h0; u.y = *(uint32_t*)&h1;
        u.z = *(uint32_t*)&h2; u.w = *(uint32_t*)&h3;
        *(uint4*)(d + i) = u;
    }
}

// yt = z_next @ C^T + (ut*dt) @ D^T  -> out[4096*512 + r*25 + n]  (fp32 exact)
__global__ void yt_k(const float* __restrict__ ut, const float* __restrict__ Cm,
                     const float* __restrict__ Dm, const float* __restrict__ dtp,
                     float* __restrict__ out)
{
    const int i = blockIdx.x * blockDim.x + threadIdx.x;
    if (i >= BATCH * 25) return;
    const int r = i / 25;
    const int n = i - r * 25;

    const float4* zr = (const float4*)(g_zbuf + (size_t)r * DDIM);
    const float4* cr = (const float4*)(Cm + (size_t)n * DDIM);
    float acc = 0.f;
#pragma unroll 8
    for (int k = 0; k < DDIM / 4; k++) {
        float4 a = zr[k], b = cr[k];
        acc += a.x * b.x + a.y * b.y + a.z * b.z + a.w * b.w;
    }
    const float4* ur = (const float4*)(ut + (size_t)r * 64);
    const float4* dr = (const float4*)(Dm + (size_t)n * 64);
    float acc2 = 0.f;
#pragma unroll
    for (int k = 0; k < 16; k++) {
        float4 a = ur[k], b = dr[k];
        acc2 += a.x * b.x + a.y * b.y + a.z * b.z + a.w * b.w;
    }
    out[(size_t)BATCH * DDIM + i] = acc + (*dtp) * acc2;
}

// ===========================================================================
extern "C" void kernel_launch(void* const* d_in, const int* in_sizes, int n_in,
                              void* d_out, int out_size)
{
    (void)in_sizes; (void)n_in; (void)out_size;

    const float* z_dyn = (const float*)d_in[0];
    /* d_in[1] = z_static : unused by reference */
    const float* dtp   = (const float*)d_in[2];
    const float* ut    = (const float*)d_in[3];
    const float* eps   = (const float*)d_in[4];
    const float* W1  = (const float*)d_in[5];
    const float* b1  = (const float*)d_in[6];
    const float* g1  = (const float*)d_in[7];
    const float* be1 = (const float*)d_in[8];
    const float* W2  = (const float*)d_in[9];
    const float* b2  = (const float*)d_in[10];
    const float* g2  = (const float*)d_in[11];
    const float* be2 = (const float*)d_in[12];
    const float* W3  = (const float*)d_in[13];
    const float* b3  = (const float*)d_in[14];
    const float* Wd1 = (const float*)d_in[15];
    const float* bd1 = (const float*)d_in[16];
    const float* Wd2 = (const float*)d_in[17];
    const float* bd2 = (const float*)d_in[18];
    const float* Bsde= (const float*)d_in[19];
    const float* Cm  = (const float*)d_in[20];
    const float* Dm  = (const float*)d_in[21];
    float* out = (float*)d_out;

    float* zbuf;
    cudaGetSymbolAddress((void**)&zbuf, g_zbuf);

    cudaFuncSetAttribute(gemm16<0>, cudaFuncAttributeMaxDynamicSharedMemorySize, SMEM_SZ);
    cudaFuncSetAttribute(gemm16<1>, cudaFuncAttributeMaxDynamicSharedMemorySize, SMEM_SZ);
    cudaFuncSetAttribute(gemm16<2>, cudaFuncAttributeMaxDynamicSharedMemorySize, SMEM_SZ);
    cudaFuncSetAttribute(gemm16<3>, cudaFuncAttributeMaxDynamicSharedMemorySize, SMEM_SZ);

    const dim3 blk(256);

    // one-shot conversions (weights, ut, z)
    cvt_all<<<dim3(256, 8), 256>>>(W1, W2, W3, Wd1, Wd2, Bsde, ut, z_dyn);

    for (int s = 0; s < NSTEPS; s++) {
        const float* eps_s = eps + (size_t)s * BATCH * DDIM;
        const float* zsrc  = (s == 0) ? z_dyn : zbuf;

        // [drift L1 | diffusion L1] fused; A1h raw + BN1 stats; Th = tanh
        gemm16<0><<<dim3(12, 32), blk, SMEM_SZ>>>(b1, bd1, nullptr, nullptr);
        // BN1 finish (scale/shift only; transform fused into MODE1 staging)
        bnstat_final<<<16, 256>>>(g1, be1);
        // drift L2: bn_relu(A1h)@W2^T; A2h raw + BN2 stats
        gemm16<1><<<dim3(8, 32), blk, SMEM_SZ>>>(b2, nullptr, nullptr, nullptr);
        // BN2 finish
        bnstat_final<<<16, 256>>>(g2, be2);
        // [drift L3 -> Fh | diffusion L2 -> softplus -> Gh]; BN2 fused in staging
        gemm16<2><<<dim3(8, 32), blk, SMEM_SZ>>>(b3, bd2, nullptr, nullptr);
        // Euler-Maruyama update
        z_update<<<(BATCH * DDIM / 4 + 255) / 256, 256>>>(dtp, eps_s, zsrc);
    }

    // z_next = z + dt*(ut @ B_sde^T) -> zbuf and out[0 : 4096*512)
    gemm16<3><<<dim3(4, 32), blk, SMEM_SZ>>>(nullptr, nullptr, dtp, out);
    // yt -> out[4096*512 : +4096*25)
    yt_k<<<(BATCH * 25 + 255) / 256, 256>>>(ut, Cm, Dm, dtp, out);
}